// round 1
// baseline (speedup 1.0000x reference)
#include <cuda_runtime.h>
#include <math.h>

#define CDIM 512
#define NPOS 16384   // T*H*W = 16*32*32

// Scratch (device globals: no allocation allowed)
__device__ float g_H [CDIM*NPOS];
__device__ float g_Q [CDIM*NPOS];
__device__ float g_K [CDIM*NPOS];
__device__ float g_V [CDIM*NPOS];
__device__ float g_O [CDIM*NPOS];
__device__ float g_X1[CDIM*NPOS];
__device__ float g_S [16*1024*1024];   // spatial attention scores [t][l][m]

// ---------------------------------------------------------------------------
// RMS norm over channel dim: for each position n (t*1024+hw), norm over c.
// H[c][n] = X[c][n] / max(||X[:,n]||, 1e-12) * sqrt(C) * gamma[c]
// ---------------------------------------------------------------------------
__global__ void rms_kernel(const float* __restrict__ X, float* __restrict__ H,
                           const float* __restrict__ gamma)
{
    int n = blockIdx.x * blockDim.x + threadIdx.x;
    float ss = 0.f;
    #pragma unroll 8
    for (int c = 0; c < CDIM; c++) {
        float v = X[(size_t)c * NPOS + n];
        ss += v * v;
    }
    float inv = 22.62741699796952f / fmaxf(sqrtf(ss), 1e-12f); // sqrt(512)/norm
    #pragma unroll 8
    for (int c = 0; c < CDIM; c++) {
        H[(size_t)c * NPOS + n] = X[(size_t)c * NPOS + n] * inv * gamma[c];
    }
}

// ---------------------------------------------------------------------------
// Generic tiled SGEMM: C[m,n] = scale * sum_k a(m,k)*b(k,n) (+bias[m]) (+Res)
//   TA=0: a(m,k)=A[m*lda+k]   TA=1: a(m,k)=A[k*lda+m]
//   TB=0: b(k,n)=B[k*ldb+n]   TB=1: b(k,n)=B[n*ldb+k]
// BM=BN=64, BK=16, 256 threads, 4x4 per thread. Dims must divide tiles.
// ---------------------------------------------------------------------------
template<int TA, int TB, bool BIAS, bool RES>
__global__ void __launch_bounds__(256)
gemm_kernel(const float* __restrict__ A, const float* __restrict__ B,
            float* __restrict__ C, const float* __restrict__ bias,
            const float* __restrict__ Res,
            int M, int N, int K,
            int lda, int ldb, int ldc,
            long sA, long sB, long sC,
            float scale)
{
    const int BM = 64, BN = 64, BK = 16;
    __shared__ float As[BK][BM];
    __shared__ float Bs[BK][BN];

    int bz = blockIdx.z;
    A += bz * sA;  B += bz * sB;  C += bz * sC;
    if (RES) Res += bz * sC;

    int bm = blockIdx.y * BM;
    int bn = blockIdx.x * BN;
    int tid = threadIdx.x;
    int tx = tid & 15, ty = tid >> 4;

    float acc[4][4] = {};

    for (int k0 = 0; k0 < K; k0 += BK) {
        if (TA == 0) {
            int m = tid >> 2;
            int k = (tid & 3) * 4;
            float4 v = *reinterpret_cast<const float4*>(A + (long)(bm + m) * lda + k0 + k);
            As[k + 0][m] = v.x; As[k + 1][m] = v.y; As[k + 2][m] = v.z; As[k + 3][m] = v.w;
        } else {
            int k = tid >> 4;
            int m = (tid & 15) * 4;
            float4 v = *reinterpret_cast<const float4*>(A + (long)(k0 + k) * lda + bm + m);
            *reinterpret_cast<float4*>(&As[k][m]) = v;
        }
        if (TB == 0) {
            int k = tid >> 4;
            int n = (tid & 15) * 4;
            float4 v = *reinterpret_cast<const float4*>(B + (long)(k0 + k) * ldb + bn + n);
            *reinterpret_cast<float4*>(&Bs[k][n]) = v;
        } else {
            int n = tid >> 2;
            int k = (tid & 3) * 4;
            float4 v = *reinterpret_cast<const float4*>(B + (long)(bn + n) * ldb + k0 + k);
            Bs[k + 0][n] = v.x; Bs[k + 1][n] = v.y; Bs[k + 2][n] = v.z; Bs[k + 3][n] = v.w;
        }
        __syncthreads();

        #pragma unroll
        for (int kk = 0; kk < BK; kk++) {
            float4 a4 = *reinterpret_cast<const float4*>(&As[kk][ty * 4]);
            float4 b4 = *reinterpret_cast<const float4*>(&Bs[kk][tx * 4]);
            float av[4] = {a4.x, a4.y, a4.z, a4.w};
            float bv[4] = {b4.x, b4.y, b4.z, b4.w};
            #pragma unroll
            for (int i = 0; i < 4; i++)
                #pragma unroll
                for (int j = 0; j < 4; j++)
                    acc[i][j] += av[i] * bv[j];
        }
        __syncthreads();
    }

    #pragma unroll
    for (int i = 0; i < 4; i++) {
        int r = bm + ty * 4 + i;
        long idx = (long)r * ldc + bn + tx * 4;
        float4 out;
        float* o = reinterpret_cast<float*>(&out);
        #pragma unroll
        for (int j = 0; j < 4; j++) {
            float v = acc[i][j] * scale;
            if (BIAS) v += bias[r];
            o[j] = v;
        }
        if (RES) {
            float4 rv = *reinterpret_cast<const float4*>(Res + idx);
            out.x += rv.x; out.y += rv.y; out.z += rv.z; out.w += rv.w;
        }
        *reinterpret_cast<float4*>(C + idx) = out;
    }
}

// ---------------------------------------------------------------------------
// Softmax over 1024-long rows (spatial attention). One block per row.
// ---------------------------------------------------------------------------
__global__ void softmax1024(float* __restrict__ S)
{
    size_t row = blockIdx.x;
    float4* p = reinterpret_cast<float4*>(S + row * 1024);
    int tid = threadIdx.x;
    float4 v = p[tid];

    __shared__ float redm[8];
    __shared__ float reds[8];

    float mx = fmaxf(fmaxf(v.x, v.y), fmaxf(v.z, v.w));
    #pragma unroll
    for (int o = 16; o; o >>= 1) mx = fmaxf(mx, __shfl_xor_sync(0xffffffffu, mx, o));
    if ((tid & 31) == 0) redm[tid >> 5] = mx;
    __syncthreads();
    mx = redm[0];
    #pragma unroll
    for (int i = 1; i < 8; i++) mx = fmaxf(mx, redm[i]);

    v.x = __expf(v.x - mx); v.y = __expf(v.y - mx);
    v.z = __expf(v.z - mx); v.w = __expf(v.w - mx);

    float sm = v.x + v.y + v.z + v.w;
    #pragma unroll
    for (int o = 16; o; o >>= 1) sm += __shfl_xor_sync(0xffffffffu, sm, o);
    if ((tid & 31) == 0) reds[tid >> 5] = sm;
    __syncthreads();
    sm = 0.f;
    #pragma unroll
    for (int i = 0; i < 8; i++) sm += reds[i];

    float r = 1.f / sm;
    v.x *= r; v.y *= r; v.z *= r; v.w *= r;
    p[tid] = v;
}

// ---------------------------------------------------------------------------
// Temporal attention: per hw (1024 of them), T=16, causal + window.
// Block handles 32 consecutive hw. Q/K/V/O layout: [c][t*1024 + hw].
// ---------------------------------------------------------------------------
__global__ void __launch_bounds__(256)
temporal_attn(const float* __restrict__ Q, const float* __restrict__ K,
              const float* __restrict__ V, float* __restrict__ O,
              const int* __restrict__ winp)
{
    __shared__ float Ss[16][16][32];   // scores/attn [i][j][hw]  (32 KB)
    __shared__ float qs[2][16][32];    // staged q chunk          (4 KB)
    __shared__ float ks[2][16][32];    // staged k chunk          (4 KB)

    const int hw0 = blockIdx.x * 32;
    const int tid = threadIdx.x;
    const int lane = tid & 31;
    const int w = tid >> 5;            // warp 0..7 -> rows {2w, 2w+1}

    float s[32];
    #pragma unroll
    for (int u = 0; u < 32; u++) s[u] = 0.f;

    for (int c0 = 0; c0 < CDIM; c0 += 2) {
        #pragma unroll
        for (int e = tid; e < 1024; e += 256) {
            int l = e & 31, i = (e >> 5) & 15, cc = e >> 9;
            long g = (long)(c0 + cc) * NPOS + i * 1024 + hw0 + l;
            qs[cc][i][l] = Q[g];
            ks[cc][i][l] = K[g];
        }
        __syncthreads();
        #pragma unroll
        for (int cc = 0; cc < 2; cc++) {
            float q0 = qs[cc][2 * w][lane];
            float q1 = qs[cc][2 * w + 1][lane];
            #pragma unroll
            for (int j = 0; j < 16; j++) {
                float kv = ks[cc][j][lane];
                s[j]      += q0 * kv;
                s[16 + j] += q1 * kv;
            }
        }
        __syncthreads();
    }

    const float scale = 0.04419417382415922f;  // 512^-0.5
    #pragma unroll
    for (int j = 0; j < 16; j++) {
        Ss[2 * w][j][lane]     = s[j] * scale;
        Ss[2 * w + 1][j][lane] = s[16 + j] * scale;
    }
    __syncthreads();

    int win = winp ? *winp : 8;

    // softmax per (i, hw): 512 rows, 2 per thread
    for (int r = tid; r < 512; r += 256) {
        int i = r >> 5, l = r & 31;
        float mx = -3.0e38f;
        #pragma unroll
        for (int j = 0; j < 16; j++) {
            bool ok = (j <= i) && (win <= 0 || (i - j) < win);
            if (ok) mx = fmaxf(mx, Ss[i][j][l]);
        }
        float e[16];
        float sum = 0.f;
        #pragma unroll
        for (int j = 0; j < 16; j++) {
            bool ok = (j <= i) && (win <= 0 || (i - j) < win);
            e[j] = ok ? __expf(Ss[i][j][l] - mx) : 0.f;
            sum += e[j];
        }
        float rinv = 1.f / sum;
        #pragma unroll
        for (int j = 0; j < 16; j++) Ss[i][j][l] = e[j] * rinv;
    }
    __syncthreads();

    // O[c][i][hw] = sum_j V[c][j][hw] * attn[i][j][hw]; warps split c.
    for (int c = w; c < CDIM; c += 8) {
        float vj[16];
        #pragma unroll
        for (int j = 0; j < 16; j++)
            vj[j] = V[(long)c * NPOS + j * 1024 + hw0 + lane];
        #pragma unroll
        for (int i = 0; i < 16; i++) {
            float o = 0.f;
            #pragma unroll
            for (int j = 0; j < 16; j++) o += vj[j] * Ss[i][j][lane];
            O[(long)c * NPOS + i * 1024 + hw0 + lane] = o;
        }
    }
}

// ---------------------------------------------------------------------------
extern "C" void kernel_launch(void* const* d_in, const int* in_sizes, int n_in,
                              void* d_out, int out_size)
{
    const float* x     = (const float*)d_in[0];
    const float* qs_w  = (const float*)d_in[1];
    const float* qs_b  = (const float*)d_in[2];
    const float* ks_w  = (const float*)d_in[3];
    const float* ks_b  = (const float*)d_in[4];
    const float* vs_w  = (const float*)d_in[5];
    const float* vs_b  = (const float*)d_in[6];
    const float* ps_w  = (const float*)d_in[7];
    const float* ps_b  = (const float*)d_in[8];
    const float* qt_w  = (const float*)d_in[9];
    const float* qt_b  = (const float*)d_in[10];
    const float* kt_w  = (const float*)d_in[11];
    const float* kt_b  = (const float*)d_in[12];
    const float* vt_w  = (const float*)d_in[13];
    const float* vt_b  = (const float*)d_in[14];
    const float* pt_w  = (const float*)d_in[15];
    const float* pt_b  = (const float*)d_in[16];
    const float* g_s   = (const float*)d_in[17];
    const float* g_t   = (const float*)d_in[18];
    const int*   winp  = (n_in > 19) ? (const int*)d_in[19] : nullptr;
    float* out = (float*)d_out;

    float *H, *Q, *K, *V, *O, *X1, *S;
    cudaGetSymbolAddress((void**)&H,  g_H);
    cudaGetSymbolAddress((void**)&Q,  g_Q);
    cudaGetSymbolAddress((void**)&K,  g_K);
    cudaGetSymbolAddress((void**)&V,  g_V);
    cudaGetSymbolAddress((void**)&O,  g_O);
    cudaGetSymbolAddress((void**)&X1, g_X1);
    cudaGetSymbolAddress((void**)&S,  g_S);

    const float scale = 0.04419417382415922f;   // 512^-0.5
    dim3 blk(256);
    dim3 gproj(NPOS / 64, CDIM / 64, 1);        // projections: M=512,N=16384,K=512
    dim3 gscore(16, 16, 16);                    // scores: M=N=1024, K=512, 16 batches
    dim3 gav(16, 8, 16);                        // AV: M=512, N=1024, K=1024, 16 batches

    // ================= spatial attention =================
    rms_kernel<<<NPOS / 256, blk>>>(x, H, g_s);
    gemm_kernel<0,0,true,false><<<gproj, blk>>>(qs_w, H, Q, qs_b, nullptr,
        512, NPOS, 512, 512, NPOS, NPOS, 0, 0, 0, 1.f);
    gemm_kernel<0,0,true,false><<<gproj, blk>>>(ks_w, H, K, ks_b, nullptr,
        512, NPOS, 512, 512, NPOS, NPOS, 0, 0, 0, 1.f);
    gemm_kernel<0,0,true,false><<<gproj, blk>>>(vs_w, H, V, vs_b, nullptr,
        512, NPOS, 512, 512, NPOS, NPOS, 0, 0, 0, 1.f);
    // S[t][l][m] = scale * sum_c Q[c][t,l] K[c][t,m]
    gemm_kernel<1,0,false,false><<<gscore, blk>>>(Q, K, S, nullptr, nullptr,
        1024, 1024, 512, NPOS, NPOS, 1024, 1024, 1024, 1024L * 1024L, scale);
    softmax1024<<<16 * 1024, blk>>>(S);
    // O[c][t,l] = sum_m V[c][t,m] attn[t][l][m]
    gemm_kernel<0,1,false,false><<<gav, blk>>>(V, S, O, nullptr, nullptr,
        512, 1024, 1024, NPOS, 1024, NPOS, 1024, 1024L * 1024L, 1024, 1.f);
    // X1 = x + ps_w @ O + ps_b
    gemm_kernel<0,0,true,true><<<gproj, blk>>>(ps_w, O, X1, ps_b, x,
        512, NPOS, 512, 512, NPOS, NPOS, 0, 0, 0, 1.f);

    // ================= temporal attention =================
    rms_kernel<<<NPOS / 256, blk>>>(X1, H, g_t);
    gemm_kernel<0,0,true,false><<<gproj, blk>>>(qt_w, H, Q, qt_b, nullptr,
        512, NPOS, 512, 512, NPOS, NPOS, 0, 0, 0, 1.f);
    gemm_kernel<0,0,true,false><<<gproj, blk>>>(kt_w, H, K, kt_b, nullptr,
        512, NPOS, 512, 512, NPOS, NPOS, 0, 0, 0, 1.f);
    gemm_kernel<0,0,true,false><<<gproj, blk>>>(vt_w, H, V, vt_b, nullptr,
        512, NPOS, 512, 512, NPOS, NPOS, 0, 0, 0, 1.f);
    temporal_attn<<<32, blk>>>(Q, K, V, O, winp);
    // out = X1 + pt_w @ O + pt_b
    gemm_kernel<0,0,true,true><<<gproj, blk>>>(pt_w, O, out, pt_b, X1,
        512, NPOS, 512, 512, NPOS, NPOS, 0, 0, 0, 1.f);
}

// round 3
// speedup vs baseline: 3.2786x; 3.2786x over previous
#include <cuda_runtime.h>
#include <cstdint>
#include <math.h>

#define CDIM 512
#define NPOS 16384   // T*H*W

// ------------------------- scratch (device globals) -------------------------
__device__ float g_XT[CDIM*NPOS];
__device__ float g_H [CDIM*NPOS];
__device__ float g_Q [CDIM*NPOS];
__device__ float g_K [CDIM*NPOS];
__device__ float g_V [CDIM*NPOS];
__device__ float g_O [CDIM*NPOS];
__device__ float g_X1[CDIM*NPOS];
__device__ float g_S [16*1024*1024];

// ------------------------- helpers -------------------------
__device__ __forceinline__ uint32_t smem_u32(const void* p){
    uint32_t a;
    asm("{ .reg .u64 t; cvta.to.shared.u64 t, %1; cvt.u32.u64 %0, t; }" : "=r"(a) : "l"(p));
    return a;
}
#define CP_ASYNC16(dst_u32, src_ptr) \
    asm volatile("cp.async.cg.shared.global [%0], [%1], 16;" :: "r"(dst_u32), "l"(src_ptr))
#define CP_COMMIT() asm volatile("cp.async.commit_group;" ::: "memory")
#define CP_WAIT1()  asm volatile("cp.async.wait_group 1;" ::: "memory")
#define CP_WAIT0()  asm volatile("cp.async.wait_group 0;" ::: "memory")

__device__ __forceinline__ uint32_t f2tf32(float v){
    uint32_t r;
    asm("cvt.rna.tf32.f32 %0, %1;" : "=r"(r) : "f"(v));
    return r;
}
__device__ __forceinline__ void mma_tf32(float* d, const uint32_t* a, const uint32_t* b){
    asm volatile(
        "mma.sync.aligned.m16n8k8.row.col.f32.tf32.tf32.f32 "
        "{%0,%1,%2,%3}, {%4,%5,%6,%7}, {%8,%9}, {%0,%1,%2,%3};"
        : "+f"(d[0]), "+f"(d[1]), "+f"(d[2]), "+f"(d[3])
        : "r"(a[0]), "r"(a[1]), "r"(a[2]), "r"(a[3]), "r"(b[0]), "r"(b[1]));
}

// ---------------------------------------------------------------------------
// tf32 mma.sync GEMM, both operands K-major:
//   C[z*czs + (y*128+r)*ldc + x*128 + s] =
//     scale * sum_k A[z*azs + (y*128+r)*lda + k] * B[z*bzs + (x*128+s)*ldb + k]
//     (+ bias) (+ Res at C's index)
// Block tile 128x128, K-chunk 32, 256 threads (8 warps, 2Mx4N), double buffer.
// ---------------------------------------------------------------------------
#define SROW 36                       // smem row stride in floats
#define BUFF (128*SROW)               // one operand buffer (floats)
#define GDSMEM (4*BUFF*4)             // bytes: A0,B0,A1,B1

__global__ void __launch_bounds__(256, 2)
gemm_mma(const float* __restrict__ A, long lda, long azs,
         const float* __restrict__ B, long ldb, long bzs,
         float* __restrict__ Cp, long ldc, long czs,
         const float* __restrict__ bias, int biasRow,
         const float* __restrict__ Res,
         int Kdim, float scale)
{
    extern __shared__ float sm[];
    const int tid  = threadIdx.x;
    const int wid  = tid >> 5;
    const int lane = tid & 31;
    const int wm   = wid >> 2;   // 0..1
    const int wn   = wid & 3;    // 0..3

    const long mRow0 = (long)blockIdx.y * 128;
    const long nCol0 = (long)blockIdx.x * 128;
    const float* Ag = A + (long)blockIdx.z * azs + mRow0 * lda;
    const float* Bg = B + (long)blockIdx.z * bzs + nCol0 * ldb;

    const uint32_t sbase = smem_u32(sm);
    const int cprow = tid >> 3;        // 0..31 base row helper
    const int cpq   = (tid & 7) * 4;   // float offset within 32-float row

    float acc[4][4][4];
    #pragma unroll
    for (int i = 0; i < 4; i++)
        #pragma unroll
        for (int j = 0; j < 4; j++)
            #pragma unroll
            for (int q = 0; q < 4; q++) acc[i][j][q] = 0.f;

    const int NC = Kdim >> 5;

    // ---- chunk loader: A/B tiles 128 rows x 32 floats each, 4 float4/thread ----
    #define LOAD_CHUNK(cc, buf) do {                                             \
        const long k0 = (long)(cc) * 32;                                         \
        uint32_t aOff = sbase + (buf) * 2*BUFF*4;                                \
        uint32_t bOff = aOff + BUFF*4;                                           \
        _Pragma("unroll")                                                        \
        for (int i = 0; i < 4; i++) {                                            \
            int row = cprow + i*32;                                              \
            CP_ASYNC16(aOff + (row*SROW + cpq)*4, Ag + (long)row*lda + k0 + cpq);\
            CP_ASYNC16(bOff + (row*SROW + cpq)*4, Bg + (long)row*ldb + k0 + cpq);\
        }                                                                        \
        CP_COMMIT();                                                             \
    } while(0)

    LOAD_CHUNK(0, 0);

    for (int c = 0; c < NC; ++c) {
        if (c + 1 < NC) { LOAD_CHUNK(c + 1, (c + 1) & 1); CP_WAIT1(); }
        else            { CP_WAIT0(); }
        __syncthreads();

        const float* cA = sm + (c & 1) * 2*BUFF + (wm*64)*SROW;
        const float* cB = sm + (c & 1) * 2*BUFF + BUFF + (wn*32)*SROW;
        const int rA = lane >> 2;          // 0..7
        const int kA = lane & 3;           // 0..3

        #pragma unroll
        for (int ks = 0; ks < 4; ks++) {
            const int col = ks*8 + kA;
            uint32_t af[4][4];
            #pragma unroll
            for (int mi = 0; mi < 4; mi++) {
                const float* p = cA + (mi*16 + rA) * SROW + col;
                af[mi][0] = f2tf32(p[0]);
                af[mi][1] = f2tf32(p[8*SROW]);
                af[mi][2] = f2tf32(p[4]);
                af[mi][3] = f2tf32(p[8*SROW + 4]);
            }
            uint32_t bf[4][2];
            #pragma unroll
            for (int ni = 0; ni < 4; ni++) {
                const float* p = cB + (ni*8 + rA) * SROW + col;
                bf[ni][0] = f2tf32(p[0]);
                bf[ni][1] = f2tf32(p[4]);
            }
            #pragma unroll
            for (int mi = 0; mi < 4; mi++)
                #pragma unroll
                for (int ni = 0; ni < 4; ni++)
                    mma_tf32(acc[mi][ni], af[mi], bf[ni]);
        }
        __syncthreads();
    }

    // ---- epilogue ----
    const long rBase = mRow0 + wm*64 + (lane >> 2);
    const long cBase = nCol0 + wn*32 + (lane & 3) * 2;
    #pragma unroll
    for (int mi = 0; mi < 4; mi++) {
        #pragma unroll
        for (int half = 0; half < 2; half++) {
            const long r = rBase + mi*16 + half*8;
            float* dst = Cp + (long)blockIdx.z * czs + r * ldc;
            const float* res = Res ? (Res + (long)blockIdx.z * czs + r * ldc) : nullptr;
            float bvr = (bias && biasRow) ? __ldg(bias + r) : 0.f;
            #pragma unroll
            for (int ni = 0; ni < 4; ni++) {
                const long cc = cBase + ni*8;
                float v0 = acc[mi][ni][half*2 + 0] * scale;
                float v1 = acc[mi][ni][half*2 + 1] * scale;
                if (bias) {
                    if (biasRow) { v0 += bvr; v1 += bvr; }
                    else { v0 += __ldg(bias + cc); v1 += __ldg(bias + cc + 1); }
                }
                if (res) {
                    float2 rv = *reinterpret_cast<const float2*>(res + cc);
                    v0 += rv.x; v1 += rv.y;
                }
                float2 o; o.x = v0; o.y = v1;
                *reinterpret_cast<float2*>(dst + cc) = o;
            }
        }
    }
}

// ---------------------------------------------------------------------------
// Transpose: out[c][r] = in[r][c], in is [R, C_]
// ---------------------------------------------------------------------------
__global__ void transpose_k(const float* __restrict__ in, float* __restrict__ out,
                            int R, int C_)
{
    __shared__ float t[32][33];
    int bx = blockIdx.x * 32;   // col of in
    int by = blockIdx.y * 32;   // row of in
    int tx = threadIdx.x, ty = threadIdx.y;
    #pragma unroll
    for (int i = 0; i < 4; i++)
        t[ty + 8*i][tx] = in[(long)(by + ty + 8*i) * C_ + bx + tx];
    __syncthreads();
    #pragma unroll
    for (int i = 0; i < 4; i++)
        out[(long)(bx + ty + 8*i) * R + by + tx] = t[tx][ty + 8*i];
}

// ---------------------------------------------------------------------------
// RMS over rows of Xt [NPOS, 512]
// ---------------------------------------------------------------------------
__global__ void __launch_bounds__(128)
rms_rows(const float* __restrict__ Xt, float* __restrict__ Ht,
         const float* __restrict__ gamma)
{
    __shared__ float red[4];
    int row = blockIdx.x;
    int tid = threadIdx.x;
    const float4 v = reinterpret_cast<const float4*>(Xt + (long)row * 512)[tid];
    float ss = v.x*v.x + v.y*v.y + v.z*v.z + v.w*v.w;
    #pragma unroll
    for (int o = 16; o; o >>= 1) ss += __shfl_xor_sync(0xffffffffu, ss, o);
    if ((tid & 31) == 0) red[tid >> 5] = ss;
    __syncthreads();
    ss = red[0] + red[1] + red[2] + red[3];
    float inv = 22.62741699796952f / fmaxf(sqrtf(ss), 1e-12f);
    float4 g = reinterpret_cast<const float4*>(gamma)[tid];
    float4 o;
    o.x = v.x * inv * g.x; o.y = v.y * inv * g.y;
    o.z = v.z * inv * g.z; o.w = v.w * inv * g.w;
    reinterpret_cast<float4*>(Ht + (long)row * 512)[tid] = o;
}

// ---------------------------------------------------------------------------
// Softmax over 1024-long rows
// ---------------------------------------------------------------------------
__global__ void softmax1024(float* __restrict__ S)
{
    size_t row = blockIdx.x;
    float4* p = reinterpret_cast<float4*>(S + row * 1024);
    int tid = threadIdx.x;
    float4 v = p[tid];

    __shared__ float redm[8];
    __shared__ float reds[8];

    float mx = fmaxf(fmaxf(v.x, v.y), fmaxf(v.z, v.w));
    #pragma unroll
    for (int o = 16; o; o >>= 1) mx = fmaxf(mx, __shfl_xor_sync(0xffffffffu, mx, o));
    if ((tid & 31) == 0) redm[tid >> 5] = mx;
    __syncthreads();
    mx = redm[0];
    #pragma unroll
    for (int i = 1; i < 8; i++) mx = fmaxf(mx, redm[i]);

    v.x = __expf(v.x - mx); v.y = __expf(v.y - mx);
    v.z = __expf(v.z - mx); v.w = __expf(v.w - mx);

    float sm = v.x + v.y + v.z + v.w;
    #pragma unroll
    for (int o = 16; o; o >>= 1) sm += __shfl_xor_sync(0xffffffffu, sm, o);
    if ((tid & 31) == 0) reds[tid >> 5] = sm;
    __syncthreads();
    sm = 0.f;
    #pragma unroll
    for (int i = 0; i < 8; i++) sm += reds[i];

    float r = 1.f / sm;
    v.x *= r; v.y *= r; v.z *= r; v.w *= r;
    p[tid] = v;
}

// ---------------------------------------------------------------------------
// Temporal attention, transposed layout. Block = one hw (1024 blocks, 128 thr).
// Qt/Kt/Vt/Ot: [NPOS, 512], rows n = t*1024 + hw.
// ---------------------------------------------------------------------------
__global__ void __launch_bounds__(128)
temporal_t(const float* __restrict__ Qt, const float* __restrict__ Kt,
           const float* __restrict__ Vt, float* __restrict__ Ot,
           const int* __restrict__ winp)
{
    __shared__ float kv[16][512];
    __shared__ float at[16][16];
    const int hw = blockIdx.x;
    const int tid = threadIdx.x;
    const int wid = tid >> 5, lane = tid & 31;
    const float scale = 0.04419417382415922f;

    for (int idx = tid; idx < 8192; idx += 128) {
        int t = idx >> 9, c = idx & 511;
        kv[t][c] = Kt[((long)(t*1024 + hw)) * 512 + c];
    }
    __syncthreads();

    #pragma unroll
    for (int ii = 0; ii < 4; ii++) {
        int i = wid + ii*4;
        float qv[16];
        const float* qr = Qt + ((long)(i*1024 + hw)) * 512;
        #pragma unroll
        for (int u = 0; u < 16; u++) qv[u] = qr[lane + 32*u];
        #pragma unroll
        for (int j = 0; j < 16; j++) {
            float s = 0.f;
            #pragma unroll
            for (int u = 0; u < 16; u++) s += qv[u] * kv[j][lane + 32*u];
            #pragma unroll
            for (int o = 16; o; o >>= 1) s += __shfl_xor_sync(0xffffffffu, s, o);
            if (lane == 0) at[i][j] = s * scale;
        }
    }
    __syncthreads();

    int win = winp ? *winp : 8;
    if (tid < 16) {
        int i = tid;
        float mx = -3.0e38f;
        #pragma unroll
        for (int j = 0; j < 16; j++) {
            bool ok = (j <= i) && (win <= 0 || (i - j) < win);
            if (ok) mx = fmaxf(mx, at[i][j]);
        }
        float sum = 0.f, e[16];
        #pragma unroll
        for (int j = 0; j < 16; j++) {
            bool ok = (j <= i) && (win <= 0 || (i - j) < win);
            e[j] = ok ? __expf(at[i][j] - mx) : 0.f;
            sum += e[j];
        }
        float rinv = 1.f / sum;
        #pragma unroll
        for (int j = 0; j < 16; j++) at[i][j] = e[j] * rinv;
    }
    __syncthreads();

    for (int idx = tid; idx < 8192; idx += 128) {
        int t = idx >> 9, c = idx & 511;
        kv[t][c] = Vt[((long)(t*1024 + hw)) * 512 + c];
    }
    __syncthreads();

    #pragma unroll
    for (int ii = 0; ii < 4; ii++) {
        int i = wid + ii*4;
        float a[16];
        #pragma unroll
        for (int j = 0; j < 16; j++) a[j] = at[i][j];
        float* orow = Ot + ((long)(i*1024 + hw)) * 512;
        #pragma unroll
        for (int u = 0; u < 16; u++) {
            float o = 0.f;
            #pragma unroll
            for (int j = 0; j < 16; j++) o += a[j] * kv[j][lane + 32*u];
            orow[lane + 32*u] = o;
        }
    }
}

// ---------------------------------------------------------------------------
extern "C" void kernel_launch(void* const* d_in, const int* in_sizes, int n_in,
                              void* d_out, int out_size)
{
    const float* x     = (const float*)d_in[0];
    const float* qs_w  = (const float*)d_in[1];
    const float* qs_b  = (const float*)d_in[2];
    const float* ks_w  = (const float*)d_in[3];
    const float* ks_b  = (const float*)d_in[4];
    const float* vs_w  = (const float*)d_in[5];
    const float* vs_b  = (const float*)d_in[6];
    const float* ps_w  = (const float*)d_in[7];
    const float* ps_b  = (const float*)d_in[8];
    const float* qt_w  = (const float*)d_in[9];
    const float* qt_b  = (const float*)d_in[10];
    const float* kt_w  = (const float*)d_in[11];
    const float* kt_b  = (const float*)d_in[12];
    const float* vt_w  = (const float*)d_in[13];
    const float* vt_b  = (const float*)d_in[14];
    const float* pt_w  = (const float*)d_in[15];
    const float* pt_b  = (const float*)d_in[16];
    const float* gm_s  = (const float*)d_in[17];
    const float* gm_t  = (const float*)d_in[18];
    const int*   winp  = (n_in > 19) ? (const int*)d_in[19] : nullptr;
    float* out = (float*)d_out;

    float *XT, *H, *Q, *K, *V, *O, *X1, *S;
    cudaGetSymbolAddress((void**)&XT, g_XT);
    cudaGetSymbolAddress((void**)&H,  g_H);
    cudaGetSymbolAddress((void**)&Q,  g_Q);
    cudaGetSymbolAddress((void**)&K,  g_K);
    cudaGetSymbolAddress((void**)&V,  g_V);
    cudaGetSymbolAddress((void**)&O,  g_O);
    cudaGetSymbolAddress((void**)&X1, g_X1);
    cudaGetSymbolAddress((void**)&S,  g_S);

    static int attr_set = 0;
    if (!attr_set) {
        cudaFuncSetAttribute(gemm_mma, cudaFuncAttributeMaxDynamicSharedMemorySize, GDSMEM);
        attr_set = 1;
    }

    const float scale = 0.04419417382415922f;   // 512^-0.5
    const long ZB = 1024L * 512;                // Q/K/O batch row-block stride
    const long ZS = 1L << 20;                   // S batch stride

    // ---- spatial ----
    transpose_k<<<dim3(512, 16), dim3(32, 8)>>>(x, XT, 512, NPOS);
    rms_rows<<<NPOS, 128>>>(XT, H, gm_s);

    // Q/K in [n, c]: grid (N=512/128, M=16384/128)
    gemm_mma<<<dim3(4, 128, 1), 256, GDSMEM>>>(H, 512, 0,  qs_w, 512, 0,  Q, 512, 0,
                                               qs_b, 0, nullptr, 512, 1.f);
    gemm_mma<<<dim3(4, 128, 1), 256, GDSMEM>>>(H, 512, 0,  ks_w, 512, 0,  K, 512, 0,
                                               ks_b, 0, nullptr, 512, 1.f);
    // V in ORIGINAL layout [c, n]: M=512 (c rows), N=16384 (positions)
    gemm_mma<<<dim3(128, 4, 1), 256, GDSMEM>>>(vs_w, 512, 0,  H, 512, 0,  V, NPOS, 0,
                                               vs_b, 1, nullptr, 512, 1.f);
    // scores S[t][l][m]: M=N=1024, K=512, 16 batches
    gemm_mma<<<dim3(8, 8, 16), 256, GDSMEM>>>(Q, 512, ZB,  K, 512, ZB,  S, 1024, ZS,
                                              nullptr, 0, nullptr, 512, scale);
    softmax1024<<<16*1024, 256>>>(S);
    // O[t*1024+l][c] = sum_m attn[l][m] V[c][t*1024+m]: M=1024, N=512, K=1024
    gemm_mma<<<dim3(4, 8, 16), 256, GDSMEM>>>(S, 1024, ZS,  V, NPOS, 1024,  O, 512, ZB,
                                              nullptr, 0, nullptr, 1024, 1.f);
    // X1 = XT + ps(O)
    gemm_mma<<<dim3(4, 128, 1), 256, GDSMEM>>>(O, 512, 0,  ps_w, 512, 0,  X1, 512, 0,
                                               ps_b, 0, XT, 512, 1.f);

    // ---- temporal ----
    rms_rows<<<NPOS, 128>>>(X1, H, gm_t);
    gemm_mma<<<dim3(4, 128, 1), 256, GDSMEM>>>(H, 512, 0,  qt_w, 512, 0,  Q, 512, 0,
                                               qt_b, 0, nullptr, 512, 1.f);
    gemm_mma<<<dim3(4, 128, 1), 256, GDSMEM>>>(H, 512, 0,  kt_w, 512, 0,  K, 512, 0,
                                               kt_b, 0, nullptr, 512, 1.f);
    gemm_mma<<<dim3(4, 128, 1), 256, GDSMEM>>>(H, 512, 0,  vt_w, 512, 0,  V, 512, 0,
                                               vt_b, 0, nullptr, 512, 1.f);
    temporal_t<<<1024, 128>>>(Q, K, V, O, winp);
    // Z = X1 + pt(O)  -> XT buffer
    gemm_mma<<<dim3(4, 128, 1), 256, GDSMEM>>>(O, 512, 0,  pt_w, 512, 0,  XT, 512, 0,
                                               pt_b, 0, X1, 512, 1.f);
    // back to [c, n]
    transpose_k<<<dim3(16, 512), dim3(32, 8)>>>(XT, out, NPOS, 512);
}

// round 4
// speedup vs baseline: 5.0410x; 1.5376x over previous
#include <cuda_runtime.h>
#include <cuda_fp16.h>
#include <cstdint>
#include <math.h>

#define CDIM 512
#define NPOS 16384   // T*H*W
#define NELEM (CDIM*NPOS)

// ------------------------- scratch (device globals) -------------------------
__device__ float  g_XT[NELEM];           // fp32 residual carrier
__device__ float  g_X1[NELEM];           // fp32 residual carrier
__device__ float  g_S [16*1024*1024];    // fp32 scores
__device__ __half g_H [NELEM];
__device__ __half g_Q [NELEM];
__device__ __half g_K [NELEM];
__device__ __half g_V [NELEM];
__device__ __half g_O [NELEM];
__device__ __half g_P [16*1024*1024];    // fp16 attention probs
__device__ __half g_W [8*CDIM*CDIM];     // fp16 weights

// ------------------------- helpers -------------------------
__device__ __forceinline__ uint32_t smem_u32(const void* p){
    uint32_t a;
    asm("{ .reg .u64 t; cvta.to.shared.u64 t, %1; cvt.u32.u64 %0, t; }" : "=r"(a) : "l"(p));
    return a;
}
#define CP_ASYNC16(dst_u32, src_ptr) \
    asm volatile("cp.async.cg.shared.global [%0], [%1], 16;" :: "r"(dst_u32), "l"(src_ptr))
#define CP_COMMIT() asm volatile("cp.async.commit_group;" ::: "memory")
#define CP_WAIT0()  asm volatile("cp.async.wait_group 0;" ::: "memory")
#define CP_WAIT1()  asm volatile("cp.async.wait_group 1;" ::: "memory")
#define CP_WAIT2()  asm volatile("cp.async.wait_group 2;" ::: "memory")

__device__ __forceinline__ void mma_f16(float* d, const uint32_t* a, const uint32_t* b){
    asm volatile(
        "mma.sync.aligned.m16n8k16.row.col.f32.f16.f16.f32 "
        "{%0,%1,%2,%3}, {%4,%5,%6,%7}, {%8,%9}, {%0,%1,%2,%3};"
        : "+f"(d[0]), "+f"(d[1]), "+f"(d[2]), "+f"(d[3])
        : "r"(a[0]), "r"(a[1]), "r"(a[2]), "r"(a[3]), "r"(b[0]), "r"(b[1]));
}

// ---------------------------------------------------------------------------
// fp16 mma.sync GEMM, both operands K-major:
//   C[z*czs + (y*128+r)*ldc + x*128 + s] =
//     scale * sum_k A[z*azs + (y*128+r)*lda + k] * B[z*bzs + (x*128+s)*ldb + k]
//     (+ bias[row or col], fp32) (+ Res fp32, only with fp32 out)
// Block 128x128, BK=32, 256 threads (2x4 warps), 4-stage cp.async pipeline.
// ---------------------------------------------------------------------------
#define BK     32
#define ROWB   80                    // bytes per smem row (32 halfs + 8 pad)
#define STAGEB (128*ROWB*2)          // A+B per stage = 20480 B
#define NSTAGE 4
#define GDSMEM (STAGEB*NSTAGE)       // 81920 B

template<bool OUTH>
__global__ void __launch_bounds__(256, 2)
gemm_h(const __half* __restrict__ A, long lda, long azs,
       const __half* __restrict__ B, long ldb, long bzs,
       void* __restrict__ Cp, long ldc, long czs,
       const float* __restrict__ bias, int biasRow,
       const float* __restrict__ Res,
       int Kdim, float scale)
{
    extern __shared__ char sm[];
    const int tid  = threadIdx.x;
    const int wid  = tid >> 5;
    const int lane = tid & 31;
    const int wm   = wid >> 2;   // 0..1
    const int wn   = wid & 3;    // 0..3

    const long mRow0 = (long)blockIdx.y * 128;
    const long nCol0 = (long)blockIdx.x * 128;
    const __half* Ag = A + (long)blockIdx.z * azs + mRow0 * lda;
    const __half* Bg = B + (long)blockIdx.z * bzs + nCol0 * ldb;

    const uint32_t sbase = smem_u32(sm);
    const int lrow = tid >> 2;        // 0..63
    const int lq   = tid & 3;         // quarter (16B)

    float acc[4][4][4];
    #pragma unroll
    for (int i = 0; i < 4; i++)
        #pragma unroll
        for (int j = 0; j < 4; j++)
            #pragma unroll
            for (int q = 0; q < 4; q++) acc[i][j][q] = 0.f;

    const int NC = Kdim >> 5;   // BK=32

    // per-chunk loader: each operand 128 rows x 64B  (2 cp16/thread/operand)
    #define LOADC(cc, st) do {                                                    \
        const long k0 = (long)(cc) * BK;                                          \
        uint32_t dA = sbase + (st)*STAGEB;                                        \
        uint32_t dB = dA + 128*ROWB;                                              \
        _Pragma("unroll")                                                         \
        for (int i = 0; i < 2; i++) {                                             \
            int row = lrow + i*64;                                                \
            CP_ASYNC16(dA + row*ROWB + lq*16, Ag + (long)row*lda + k0 + lq*8);    \
            CP_ASYNC16(dB + row*ROWB + lq*16, Bg + (long)row*ldb + k0 + lq*8);    \
        }                                                                         \
        CP_COMMIT();                                                              \
    } while(0)

    // prefetch 3 chunks (NC is always >= 16 here)
    LOADC(0, 0); LOADC(1, 1); LOADC(2, 2);
    CP_WAIT2();
    __syncthreads();

    const int rA = lane >> 2;          // 0..7
    const int kA = lane & 3;           // 0..3

    for (int c = 0; c < NC; ++c) {
        if (c + 3 < NC) LOADC(c + 3, (c + 3) & 3);

        const char* baseA = sm + (c & 3)*STAGEB + (wm*64)*ROWB;
        const char* baseB = sm + (c & 3)*STAGEB + 128*ROWB + (wn*32)*ROWB;

        #pragma unroll
        for (int ks = 0; ks < 2; ks++) {
            const int kb = ks*32 + kA*4;        // byte offset of half2 (k = ks*16 + 2kA)
            uint32_t af[4][4];
            #pragma unroll
            for (int mi = 0; mi < 4; mi++) {
                const char* p = baseA + (mi*16 + rA)*ROWB + kb;
                af[mi][0] = *reinterpret_cast<const uint32_t*>(p);
                af[mi][1] = *reinterpret_cast<const uint32_t*>(p + 8*ROWB);
                af[mi][2] = *reinterpret_cast<const uint32_t*>(p + 16);
                af[mi][3] = *reinterpret_cast<const uint32_t*>(p + 8*ROWB + 16);
            }
            uint32_t bf[4][2];
            #pragma unroll
            for (int ni = 0; ni < 4; ni++) {
                const char* p = baseB + (ni*8 + rA)*ROWB + kb;
                bf[ni][0] = *reinterpret_cast<const uint32_t*>(p);
                bf[ni][1] = *reinterpret_cast<const uint32_t*>(p + 16);
            }
            #pragma unroll
            for (int mi = 0; mi < 4; mi++)
                #pragma unroll
                for (int ni = 0; ni < 4; ni++)
                    mma_f16(acc[mi][ni], af[mi], bf[ni]);
        }

        if (c < NC - 1) {
            const int rem = NC - 2 - c;   // groups allowed to stay pending
            if (rem >= 2)      CP_WAIT2();
            else if (rem == 1) CP_WAIT1();
            else               CP_WAIT0();
            __syncthreads();
        }
    }

    // ---- epilogue ----
    const long rBase = mRow0 + wm*64 + (lane >> 2);
    const long cBase = nCol0 + wn*32 + (lane & 3) * 2;
    #pragma unroll
    for (int mi = 0; mi < 4; mi++) {
        #pragma unroll
        for (int half_ = 0; half_ < 2; half_++) {
            const long r = rBase + mi*16 + half_*8;
            const float bvr = (bias && biasRow) ? __ldg(bias + r) : 0.f;
            const long rowOff = (long)blockIdx.z * czs + r * ldc;
            #pragma unroll
            for (int ni = 0; ni < 4; ni++) {
                const long cc = cBase + ni*8;
                float v0 = acc[mi][ni][half_*2 + 0] * scale;
                float v1 = acc[mi][ni][half_*2 + 1] * scale;
                if (bias) {
                    if (biasRow) { v0 += bvr; v1 += bvr; }
                    else { v0 += __ldg(bias + cc); v1 += __ldg(bias + cc + 1); }
                }
                if (OUTH) {
                    __half2 h = __floats2half2_rn(v0, v1);
                    *reinterpret_cast<__half2*>((__half*)Cp + rowOff + cc) = h;
                } else {
                    if (Res) {
                        float2 rv = *reinterpret_cast<const float2*>(Res + rowOff + cc);
                        v0 += rv.x; v1 += rv.y;
                    }
                    float2 o; o.x = v0; o.y = v1;
                    *reinterpret_cast<float2*>((float*)Cp + rowOff + cc) = o;
                }
            }
        }
    }
    #undef LOADC
}

// ---------------------------------------------------------------------------
// Weight conversion: 8 x [512x512] fp32 -> fp16 into g_W
// ---------------------------------------------------------------------------
__global__ void convw(const float* __restrict__ w0, const float* __restrict__ w1,
                      const float* __restrict__ w2, const float* __restrict__ w3,
                      const float* __restrict__ w4, const float* __restrict__ w5,
                      const float* __restrict__ w6, const float* __restrict__ w7,
                      __half* __restrict__ W)
{
    long i = (long)blockIdx.x * 256 + threadIdx.x;   // 8*262144 total
    int sel = (int)(i >> 18);
    long off = i & 262143;
    const float* src;
    switch (sel) {
        case 0: src = w0; break; case 1: src = w1; break;
        case 2: src = w2; break; case 3: src = w3; break;
        case 4: src = w4; break; case 5: src = w5; break;
        case 6: src = w6; break; default: src = w7; break;
    }
    W[i] = __float2half_rn(src[off]);
}

// ---------------------------------------------------------------------------
// Transpose: out[c][r] = in[r][c], in is [R, C_]  (fp32)
// ---------------------------------------------------------------------------
__global__ void transpose_k(const float* __restrict__ in, float* __restrict__ out,
                            int R, int C_)
{
    __shared__ float t[32][33];
    int bx = blockIdx.x * 32;
    int by = blockIdx.y * 32;
    int tx = threadIdx.x, ty = threadIdx.y;
    #pragma unroll
    for (int i = 0; i < 4; i++)
        t[ty + 8*i][tx] = in[(long)(by + ty + 8*i) * C_ + bx + tx];
    __syncthreads();
    #pragma unroll
    for (int i = 0; i < 4; i++)
        out[(long)(bx + ty + 8*i) * R + by + tx] = t[tx][ty + 8*i];
}

// ---------------------------------------------------------------------------
// RMS over rows of Xt [NPOS, 512] fp32 -> fp16
// ---------------------------------------------------------------------------
__global__ void __launch_bounds__(128)
rms_rows(const float* __restrict__ Xt, __half* __restrict__ Ht,
         const float* __restrict__ gamma)
{
    __shared__ float red[4];
    int row = blockIdx.x;
    int tid = threadIdx.x;
    const float4 v = reinterpret_cast<const float4*>(Xt + (long)row * 512)[tid];
    float ss = v.x*v.x + v.y*v.y + v.z*v.z + v.w*v.w;
    #pragma unroll
    for (int o = 16; o; o >>= 1) ss += __shfl_xor_sync(0xffffffffu, ss, o);
    if ((tid & 31) == 0) red[tid >> 5] = ss;
    __syncthreads();
    ss = red[0] + red[1] + red[2] + red[3];
    float inv = 22.62741699796952f / fmaxf(sqrtf(ss), 1e-12f);
    float4 g = reinterpret_cast<const float4*>(gamma)[tid];
    __half2 h0 = __floats2half2_rn(v.x * inv * g.x, v.y * inv * g.y);
    __half2 h1 = __floats2half2_rn(v.z * inv * g.z, v.w * inv * g.w);
    __half2* dst = reinterpret_cast<__half2*>(Ht + (long)row * 512 + tid * 4);
    dst[0] = h0; dst[1] = h1;
}

// ---------------------------------------------------------------------------
// Softmax over 1024-long fp32 rows -> fp16 probs
// ---------------------------------------------------------------------------
__global__ void softmax1024(const float* __restrict__ S, __half* __restrict__ P)
{
    size_t row = blockIdx.x;
    const float4* p = reinterpret_cast<const float4*>(S + row * 1024);
    int tid = threadIdx.x;
    float4 v = p[tid];

    __shared__ float redm[8];
    __shared__ float reds[8];

    float mx = fmaxf(fmaxf(v.x, v.y), fmaxf(v.z, v.w));
    #pragma unroll
    for (int o = 16; o; o >>= 1) mx = fmaxf(mx, __shfl_xor_sync(0xffffffffu, mx, o));
    if ((tid & 31) == 0) redm[tid >> 5] = mx;
    __syncthreads();
    mx = redm[0];
    #pragma unroll
    for (int i = 1; i < 8; i++) mx = fmaxf(mx, redm[i]);

    v.x = __expf(v.x - mx); v.y = __expf(v.y - mx);
    v.z = __expf(v.z - mx); v.w = __expf(v.w - mx);

    float sm = v.x + v.y + v.z + v.w;
    #pragma unroll
    for (int o = 16; o; o >>= 1) sm += __shfl_xor_sync(0xffffffffu, sm, o);
    if ((tid & 31) == 0) reds[tid >> 5] = sm;
    __syncthreads();
    sm = 0.f;
    #pragma unroll
    for (int i = 0; i < 8; i++) sm += reds[i];

    float r = 1.f / sm;
    __half2 h0 = __floats2half2_rn(v.x * r, v.y * r);
    __half2 h1 = __floats2half2_rn(v.z * r, v.w * r);
    __half2* dst = reinterpret_cast<__half2*>(P + row * 1024 + tid * 4);
    dst[0] = h0; dst[1] = h1;
}

// ---------------------------------------------------------------------------
// Temporal attention (fp16 I/O). Block = one hw, 128 threads.
// Qt/Kt/Vt/Ot: [NPOS, 512] fp16, rows n = t*1024 + hw.
// ---------------------------------------------------------------------------
__global__ void __launch_bounds__(128)
temporal_t(const __half* __restrict__ Qt, const __half* __restrict__ Kt,
           const __half* __restrict__ Vt, __half* __restrict__ Ot,
           const int* __restrict__ winp)
{
    __shared__ float kv[16][512];
    __shared__ float at[16][16];
    const int hw = blockIdx.x;
    const int tid = threadIdx.x;
    const int wid = tid >> 5, lane = tid & 31;
    const float scale = 0.04419417382415922f;

    for (int idx = tid; idx < 4096; idx += 128) {
        int t = idx >> 8, c2 = idx & 255;
        __half2 h = *reinterpret_cast<const __half2*>(Kt + ((long)(t*1024 + hw))*512 + c2*2);
        float2 f = __half22float2(h);
        kv[t][c2*2] = f.x; kv[t][c2*2+1] = f.y;
    }
    __syncthreads();

    #pragma unroll
    for (int ii = 0; ii < 4; ii++) {
        int i = wid + ii*4;
        float qv[16];
        const __half* qr = Qt + ((long)(i*1024 + hw)) * 512;
        #pragma unroll
        for (int u = 0; u < 16; u++) qv[u] = __half2float(qr[lane + 32*u]);
        #pragma unroll
        for (int j = 0; j < 16; j++) {
            float s = 0.f;
            #pragma unroll
            for (int u = 0; u < 16; u++) s += qv[u] * kv[j][lane + 32*u];
            #pragma unroll
            for (int o = 16; o; o >>= 1) s += __shfl_xor_sync(0xffffffffu, s, o);
            if (lane == 0) at[i][j] = s * scale;
        }
    }
    __syncthreads();

    int win = winp ? *winp : 8;
    if (tid < 16) {
        int i = tid;
        float mx = -3.0e38f;
        #pragma unroll
        for (int j = 0; j < 16; j++) {
            bool ok = (j <= i) && (win <= 0 || (i - j) < win);
            if (ok) mx = fmaxf(mx, at[i][j]);
        }
        float sum = 0.f, e[16];
        #pragma unroll
        for (int j = 0; j < 16; j++) {
            bool ok = (j <= i) && (win <= 0 || (i - j) < win);
            e[j] = ok ? __expf(at[i][j] - mx) : 0.f;
            sum += e[j];
        }
        float rinv = 1.f / sum;
        #pragma unroll
        for (int j = 0; j < 16; j++) at[i][j] = e[j] * rinv;
    }
    __syncthreads();

    for (int idx = tid; idx < 4096; idx += 128) {
        int t = idx >> 8, c2 = idx & 255;
        __half2 h = *reinterpret_cast<const __half2*>(Vt + ((long)(t*1024 + hw))*512 + c2*2);
        float2 f = __half22float2(h);
        kv[t][c2*2] = f.x; kv[t][c2*2+1] = f.y;
    }
    __syncthreads();

    #pragma unroll
    for (int ii = 0; ii < 4; ii++) {
        int i = wid + ii*4;
        float a[16];
        #pragma unroll
        for (int j = 0; j < 16; j++) a[j] = at[i][j];
        __half* orow = Ot + ((long)(i*1024 + hw)) * 512;
        #pragma unroll
        for (int u = 0; u < 16; u++) {
            float o = 0.f;
            #pragma unroll
            for (int j = 0; j < 16; j++) o += a[j] * kv[j][lane + 32*u];
            orow[lane + 32*u] = __float2half_rn(o);
        }
    }
}

// ---------------------------------------------------------------------------
extern "C" void kernel_launch(void* const* d_in, const int* in_sizes, int n_in,
                              void* d_out, int out_size)
{
    const float* x     = (const float*)d_in[0];
    const float* qs_w  = (const float*)d_in[1];
    const float* qs_b  = (const float*)d_in[2];
    const float* ks_w  = (const float*)d_in[3];
    const float* ks_b  = (const float*)d_in[4];
    const float* vs_w  = (const float*)d_in[5];
    const float* vs_b  = (const float*)d_in[6];
    const float* ps_w  = (const float*)d_in[7];
    const float* ps_b  = (const float*)d_in[8];
    const float* qt_w  = (const float*)d_in[9];
    const float* qt_b  = (const float*)d_in[10];
    const float* kt_w  = (const float*)d_in[11];
    const float* kt_b  = (const float*)d_in[12];
    const float* vt_w  = (const float*)d_in[13];
    const float* vt_b  = (const float*)d_in[14];
    const float* pt_w  = (const float*)d_in[15];
    const float* pt_b  = (const float*)d_in[16];
    const float* gm_s  = (const float*)d_in[17];
    const float* gm_t  = (const float*)d_in[18];
    const int*   winp  = (n_in > 19) ? (const int*)d_in[19] : nullptr;
    float* out = (float*)d_out;

    float *XT, *X1, *S;
    __half *H, *Q, *K, *V, *O, *P, *W;
    cudaGetSymbolAddress((void**)&XT, g_XT);
    cudaGetSymbolAddress((void**)&X1, g_X1);
    cudaGetSymbolAddress((void**)&S,  g_S);
    cudaGetSymbolAddress((void**)&H,  g_H);
    cudaGetSymbolAddress((void**)&Q,  g_Q);
    cudaGetSymbolAddress((void**)&K,  g_K);
    cudaGetSymbolAddress((void**)&V,  g_V);
    cudaGetSymbolAddress((void**)&O,  g_O);
    cudaGetSymbolAddress((void**)&P,  g_P);
    cudaGetSymbolAddress((void**)&W,  g_W);

    static int attr_set = 0;
    if (!attr_set) {
        cudaFuncSetAttribute(gemm_h<true>,  cudaFuncAttributeMaxDynamicSharedMemorySize, GDSMEM);
        cudaFuncSetAttribute(gemm_h<false>, cudaFuncAttributeMaxDynamicSharedMemorySize, GDSMEM);
        attr_set = 1;
    }

    const float scale = 0.04419417382415922f;   // 512^-0.5
    const long ZB = 1024L * 512;                // Q/K/O per-t row-block stride
    const long ZS = 1L << 20;                   // S/P per-t stride
    const long WS = 512L * 512;                 // per-weight stride in g_W

    // weights -> fp16 (order: qs ks vs ps qt kt vt pt)
    convw<<<8192, 256>>>(qs_w, ks_w, vs_w, ps_w, qt_w, kt_w, vt_w, pt_w, W);
    // x [c,n] -> XT [n,c] fp32
    transpose_k<<<dim3(512, 16), dim3(32, 8)>>>(x, XT, 512, NPOS);
    rms_rows<<<NPOS, 128>>>(XT, H, gm_s);

    // ---- spatial ----
    gemm_h<true><<<dim3(4, 128, 1), 256, GDSMEM>>>(H, 512, 0,  W + 0*WS, 512, 0,
        Q, 512, 0, qs_b, 0, nullptr, 512, 1.f);
    gemm_h<true><<<dim3(4, 128, 1), 256, GDSMEM>>>(H, 512, 0,  W + 1*WS, 512, 0,
        K, 512, 0, ks_b, 0, nullptr, 512, 1.f);
    // V in [c, n] layout
    gemm_h<true><<<dim3(128, 4, 1), 256, GDSMEM>>>(W + 2*WS, 512, 0,  H, 512, 0,
        V, NPOS, 0, vs_b, 1, nullptr, 512, 1.f);
    // scores S[t][l][m] fp32
    gemm_h<false><<<dim3(8, 8, 16), 256, GDSMEM>>>(Q, 512, ZB,  K, 512, ZB,
        S, 1024, ZS, nullptr, 0, nullptr, 512, scale);
    softmax1024<<<16*1024, 256>>>(S, P);
    // O[t*1024+l][c] = sum_m P[l][m] V[c][t*1024+m]
    gemm_h<true><<<dim3(4, 8, 16), 256, GDSMEM>>>(P, 1024, ZS,  V, NPOS, 1024,
        O, 512, ZB, nullptr, 0, nullptr, 1024, 1.f);
    // X1 = XT + ps(O)  (fp32)
    gemm_h<false><<<dim3(4, 128, 1), 256, GDSMEM>>>(O, 512, 0,  W + 3*WS, 512, 0,
        X1, 512, 0, ps_b, 0, XT, 512, 1.f);

    // ---- temporal ----
    rms_rows<<<NPOS, 128>>>(X1, H, gm_t);
    gemm_h<true><<<dim3(4, 128, 1), 256, GDSMEM>>>(H, 512, 0,  W + 4*WS, 512, 0,
        Q, 512, 0, qt_b, 0, nullptr, 512, 1.f);
    gemm_h<true><<<dim3(4, 128, 1), 256, GDSMEM>>>(H, 512, 0,  W + 5*WS, 512, 0,
        K, 512, 0, kt_b, 0, nullptr, 512, 1.f);
    gemm_h<true><<<dim3(4, 128, 1), 256, GDSMEM>>>(H, 512, 0,  W + 6*WS, 512, 0,
        V, 512, 0, vt_b, 0, nullptr, 512, 1.f);
    temporal_t<<<1024, 128>>>(Q, K, V, O, winp);
    // Z = X1 + pt(O)  -> XT (fp32)
    gemm_h<false><<<dim3(4, 128, 1), 256, GDSMEM>>>(O, 512, 0,  W + 7*WS, 512, 0,
        XT, 512, 0, pt_b, 0, X1, 512, 1.f);
    // back to [c, n]
    transpose_k<<<dim3(16, 512), dim3(32, 8)>>>(XT, out, NPOS, 512);
}

// round 5
// speedup vs baseline: 5.2089x; 1.0333x over previous
#include <cuda_runtime.h>
#include <cuda_fp16.h>
#include <cstdint>
#include <math.h>

#define CDIM 512
#define NPOS 16384   // T*H*W
#define NELEM (CDIM*NPOS)

// ------------------------- scratch (device globals) -------------------------
__device__ float  g_XT[NELEM];            // fp32 residual carrier [n,c]
__device__ float  g_X1[NELEM];            // fp32 residual carrier [n,c]
__device__ float  g_S [16*1024*1024];     // fp32 scores
__device__ __half g_H  [NELEM];           // rms output [n,c]
__device__ __half g_QKV[NPOS*1536];       // spatial QK (ld 1024) / temporal QKV (ld 1536)
__device__ __half g_V [NELEM];            // spatial V [c,n]
__device__ __half g_O [NELEM];            // attention out [n,c]
__device__ __half g_P [16*1024*1024];     // fp16 attention probs
__device__ __half g_W [8*CDIM*CDIM];      // fp16 weights (qs ks vs ps qt kt vt pt)
__device__ float  g_BC[4096];             // packed biases

// ------------------------- helpers -------------------------
__device__ __forceinline__ uint32_t smem_u32(const void* p){
    uint32_t a;
    asm("{ .reg .u64 t; cvta.to.shared.u64 t, %1; cvt.u32.u64 %0, t; }" : "=r"(a) : "l"(p));
    return a;
}
#define CP_ASYNC16(dst_u32, src_ptr) \
    asm volatile("cp.async.cg.shared.global [%0], [%1], 16;" :: "r"(dst_u32), "l"(src_ptr))
#define CP_COMMIT() asm volatile("cp.async.commit_group;" ::: "memory")
#define CP_WAIT0()  asm volatile("cp.async.wait_group 0;" ::: "memory")
#define CP_WAIT1()  asm volatile("cp.async.wait_group 1;" ::: "memory")
#define CP_WAIT2()  asm volatile("cp.async.wait_group 2;" ::: "memory")

__device__ __forceinline__ void mma_f16(float* d, const uint32_t* a, const uint32_t* b){
    asm volatile(
        "mma.sync.aligned.m16n8k16.row.col.f32.f16.f16.f32 "
        "{%0,%1,%2,%3}, {%4,%5,%6,%7}, {%8,%9}, {%0,%1,%2,%3};"
        : "+f"(d[0]), "+f"(d[1]), "+f"(d[2]), "+f"(d[3])
        : "r"(a[0]), "r"(a[1]), "r"(a[2]), "r"(a[3]), "r"(b[0]), "r"(b[1]));
}
__device__ __forceinline__ void ldm_x4(uint32_t* r, uint32_t addr){
    asm volatile("ldmatrix.sync.aligned.m8n8.x4.shared.b16 {%0,%1,%2,%3}, [%4];"
        : "=r"(r[0]), "=r"(r[1]), "=r"(r[2]), "=r"(r[3]) : "r"(addr));
}

// ---------------------------------------------------------------------------
// fp16 mma.sync GEMM, both operands K-major:
//   C[z*czs + (y*128+r)*ldc + x*128 + s] =
//     scale * sum_k A[z*azs + (y*128+r)*lda + k] * B[z*bzs + (x*128+s)*ldb + k]
//     (+ bias[row or col], fp32) (+ Res fp32, only fp32 out)
// Block 128x128, BK=32, 256 threads (2x4 warps), 4-stage cp.async, ldmatrix.
// ---------------------------------------------------------------------------
#define BK     32
#define ROWB   80                    // bytes per smem row (32 halfs + 8 pad)
#define STAGEB (128*ROWB*2)          // A+B per stage = 20480 B
#define GDSMEM (STAGEB*4)            // 81920 B

template<bool OUTH>
__global__ void __launch_bounds__(256, 2)
gemm_h(const __half* __restrict__ A, long lda, long azs,
       const __half* __restrict__ B, long ldb, long bzs,
       void* __restrict__ Cp, long ldc, long czs,
       const float* __restrict__ bias, int biasRow,
       const float* __restrict__ Res,
       int Kdim, float scale)
{
    extern __shared__ char sm[];
    const int tid  = threadIdx.x;
    const int wid  = tid >> 5;
    const int lane = tid & 31;
    const int wm   = wid >> 2;   // 0..1
    const int wn   = wid & 3;    // 0..3

    const long mRow0 = (long)blockIdx.y * 128;
    const long nCol0 = (long)blockIdx.x * 128;
    const __half* Ag = A + (long)blockIdx.z * azs + mRow0 * lda;
    const __half* Bg = B + (long)blockIdx.z * bzs + nCol0 * ldb;

    const uint32_t sbase = smem_u32(sm);
    const int lrow = tid >> 2;        // 0..63
    const int lq   = tid & 3;         // 16B quarter

    // per-lane ldmatrix address components
    const uint32_t lmOff = (uint32_t)(lane & 15) * ROWB + (uint32_t)(lane >> 4) * 16;

    float acc[4][4][4];
    #pragma unroll
    for (int i = 0; i < 4; i++)
        #pragma unroll
        for (int j = 0; j < 4; j++)
            #pragma unroll
            for (int q = 0; q < 4; q++) acc[i][j][q] = 0.f;

    const int NC = Kdim >> 5;

    #define LOADC(cc, st) do {                                                    \
        const long k0 = (long)(cc) * BK;                                          \
        uint32_t dA = sbase + (st)*STAGEB;                                        \
        uint32_t dB = dA + 128*ROWB;                                              \
        _Pragma("unroll")                                                         \
        for (int i = 0; i < 2; i++) {                                             \
            int row = lrow + i*64;                                                \
            CP_ASYNC16(dA + row*ROWB + lq*16, Ag + (long)row*lda + k0 + lq*8);    \
            CP_ASYNC16(dB + row*ROWB + lq*16, Bg + (long)row*ldb + k0 + lq*8);    \
        }                                                                         \
        CP_COMMIT();                                                              \
    } while(0)

    LOADC(0, 0); LOADC(1, 1); LOADC(2, 2);
    CP_WAIT2();
    __syncthreads();

    for (int c = 0; c < NC; ++c) {
        if (c + 3 < NC) LOADC(c + 3, (c + 3) & 3);

        const uint32_t stB = sbase + (c & 3)*STAGEB;
        const uint32_t aAddr = stB + (uint32_t)(wm*64)*ROWB + lmOff;
        const uint32_t bAddr = stB + 128*ROWB + (uint32_t)(wn*32)*ROWB + lmOff;

        #pragma unroll
        for (int ks = 0; ks < 2; ks++) {
            const uint32_t kOff = ks*32;
            uint32_t af[4][4];
            #pragma unroll
            for (int mi = 0; mi < 4; mi++)
                ldm_x4(af[mi], aAddr + mi*(16*ROWB) + kOff);
            uint32_t bf[4][2];
            #pragma unroll
            for (int g = 0; g < 2; g++) {
                uint32_t bq[4];
                ldm_x4(bq, bAddr + g*(16*ROWB) + kOff);
                bf[2*g+0][0] = bq[0]; bf[2*g+1][0] = bq[1];
                bf[2*g+0][1] = bq[2]; bf[2*g+1][1] = bq[3];
            }
            #pragma unroll
            for (int mi = 0; mi < 4; mi++)
                #pragma unroll
                for (int ni = 0; ni < 4; ni++)
                    mma_f16(acc[mi][ni], af[mi], bf[ni]);
        }

        if (c < NC - 1) {
            const int rem = NC - 2 - c;
            if (rem >= 2)      CP_WAIT2();
            else if (rem == 1) CP_WAIT1();
            else               CP_WAIT0();
            __syncthreads();
        }
    }

    // ---- epilogue ----
    const long rBase = mRow0 + wm*64 + (lane >> 2);
    const long cBase = nCol0 + wn*32 + (lane & 3) * 2;
    #pragma unroll
    for (int mi = 0; mi < 4; mi++) {
        #pragma unroll
        for (int half_ = 0; half_ < 2; half_++) {
            const long r = rBase + mi*16 + half_*8;
            const float bvr = (bias && biasRow) ? __ldg(bias + r) : 0.f;
            const long rowOff = (long)blockIdx.z * czs + r * ldc;
            #pragma unroll
            for (int ni = 0; ni < 4; ni++) {
                const long cc = cBase + ni*8;
                float v0 = acc[mi][ni][half_*2 + 0] * scale;
                float v1 = acc[mi][ni][half_*2 + 1] * scale;
                if (bias) {
                    if (biasRow) { v0 += bvr; v1 += bvr; }
                    else { v0 += __ldg(bias + cc); v1 += __ldg(bias + cc + 1); }
                }
                if (OUTH) {
                    __half2 h = __floats2half2_rn(v0, v1);
                    *reinterpret_cast<__half2*>((__half*)Cp + rowOff + cc) = h;
                } else {
                    if (Res) {
                        float2 rv = *reinterpret_cast<const float2*>(Res + rowOff + cc);
                        v0 += rv.x; v1 += rv.y;
                    }
                    float2 o; o.x = v0; o.y = v1;
                    *reinterpret_cast<float2*>((float*)Cp + rowOff + cc) = o;
                }
            }
        }
    }
    #undef LOADC
}

// ---------------------------------------------------------------------------
// Weight fp32->fp16 conversion + bias packing
// ---------------------------------------------------------------------------
__global__ void convw(const float* __restrict__ w0, const float* __restrict__ w1,
                      const float* __restrict__ w2, const float* __restrict__ w3,
                      const float* __restrict__ w4, const float* __restrict__ w5,
                      const float* __restrict__ w6, const float* __restrict__ w7,
                      const float* __restrict__ qsb, const float* __restrict__ ksb,
                      const float* __restrict__ qtb, const float* __restrict__ ktb,
                      const float* __restrict__ vtb,
                      __half* __restrict__ W, float* __restrict__ BC)
{
    long i = (long)blockIdx.x * 256 + threadIdx.x;
    int sel = (int)(i >> 18);
    long off = i & 262143;
    const float* src;
    switch (sel) {
        case 0: src = w0; break; case 1: src = w1; break;
        case 2: src = w2; break; case 3: src = w3; break;
        case 4: src = w4; break; case 5: src = w5; break;
        case 6: src = w6; break; default: src = w7; break;
    }
    W[i] = __float2half_rn(src[off]);
    if (i < 2560) {
        long j = i;
        if      (j < 512)  BC[j]          = qsb[j];
        else if (j < 1024) BC[j]          = ksb[j - 512];
        else if (j < 1536) BC[2048 + (j-1024)] = qtb[j - 1024];
        else if (j < 2048) BC[2560 + (j-1536)] = ktb[j - 1536];
        else               BC[3072 + (j-2048)] = vtb[j - 2048];
    }
}

// ---------------------------------------------------------------------------
// Fused transpose + RMS: x [c,n] -> XT [n,c] (fp32) + H [n,c] (fp16)
// Block = 32 positions, 256 threads, 512x33 smem tile.
// ---------------------------------------------------------------------------
#define TRMS_SMEM (512*33*4)
__global__ void __launch_bounds__(256)
trms(const float* __restrict__ x, float* __restrict__ XT, __half* __restrict__ H,
     const float* __restrict__ gamma)
{
    extern __shared__ float ts[];   // [512][33]
    __shared__ float red[8][32];
    __shared__ float invs[32];
    const int n0 = blockIdx.x * 32;
    const int tid = threadIdx.x;

    for (int idx = tid; idx < 4096; idx += 256) {
        int c = idx >> 3, q = idx & 7;
        float4 v = *reinterpret_cast<const float4*>(x + (long)c*NPOS + n0 + q*4);
        float* row = ts + c*33 + q*4;
        row[0]=v.x; row[1]=v.y; row[2]=v.z; row[3]=v.w;
    }
    __syncthreads();
    {
        int col = tid & 31, seg = tid >> 5;
        float ss = 0.f;
        #pragma unroll 8
        for (int c = seg*64; c < seg*64 + 64; c++) {
            float v = ts[c*33 + col]; ss += v*v;
        }
        red[seg][col] = ss;
    }
    __syncthreads();
    if (tid < 32) {
        float ss = 0.f;
        #pragma unroll
        for (int s = 0; s < 8; s++) ss += red[s][tid];
        invs[tid] = 22.62741699796952f / fmaxf(sqrtf(ss), 1e-12f);
    }
    __syncthreads();
    for (int idx = tid; idx < 16384; idx += 256) {
        int nl = idx >> 9, c = idx & 511;
        float v = ts[c*33 + nl];
        long o = (long)(n0 + nl) * 512 + c;
        XT[o] = v;
        H[o] = __float2half_rn(v * invs[nl] * gamma[c]);
    }
}

// ---------------------------------------------------------------------------
// RMS over rows of Xt [NPOS, 512] fp32 -> fp16
// ---------------------------------------------------------------------------
__global__ void __launch_bounds__(128)
rms_rows(const float* __restrict__ Xt, __half* __restrict__ Ht,
         const float* __restrict__ gamma)
{
    __shared__ float red[4];
    int row = blockIdx.x;
    int tid = threadIdx.x;
    const float4 v = reinterpret_cast<const float4*>(Xt + (long)row * 512)[tid];
    float ss = v.x*v.x + v.y*v.y + v.z*v.z + v.w*v.w;
    #pragma unroll
    for (int o = 16; o; o >>= 1) ss += __shfl_xor_sync(0xffffffffu, ss, o);
    if ((tid & 31) == 0) red[tid >> 5] = ss;
    __syncthreads();
    ss = red[0] + red[1] + red[2] + red[3];
    float inv = 22.62741699796952f / fmaxf(sqrtf(ss), 1e-12f);
    float4 g = reinterpret_cast<const float4*>(gamma)[tid];
    __half2 h0 = __floats2half2_rn(v.x * inv * g.x, v.y * inv * g.y);
    __half2 h1 = __floats2half2_rn(v.z * inv * g.z, v.w * inv * g.w);
    __half2* dst = reinterpret_cast<__half2*>(Ht + (long)row * 512 + tid * 4);
    dst[0] = h0; dst[1] = h1;
}

// ---------------------------------------------------------------------------
// Softmax over 1024-long fp32 rows -> fp16 probs
// ---------------------------------------------------------------------------
__global__ void softmax1024(const float* __restrict__ S, __half* __restrict__ P)
{
    size_t row = blockIdx.x;
    const float4* p = reinterpret_cast<const float4*>(S + row * 1024);
    int tid = threadIdx.x;
    float4 v = p[tid];

    __shared__ float redm[8];
    __shared__ float reds[8];

    float mx = fmaxf(fmaxf(v.x, v.y), fmaxf(v.z, v.w));
    #pragma unroll
    for (int o = 16; o; o >>= 1) mx = fmaxf(mx, __shfl_xor_sync(0xffffffffu, mx, o));
    if ((tid & 31) == 0) redm[tid >> 5] = mx;
    __syncthreads();
    mx = redm[0];
    #pragma unroll
    for (int i = 1; i < 8; i++) mx = fmaxf(mx, redm[i]);

    v.x = __expf(v.x - mx); v.y = __expf(v.y - mx);
    v.z = __expf(v.z - mx); v.w = __expf(v.w - mx);

    float sm = v.x + v.y + v.z + v.w;
    #pragma unroll
    for (int o = 16; o; o >>= 1) sm += __shfl_xor_sync(0xffffffffu, sm, o);
    if ((tid & 31) == 0) reds[tid >> 5] = sm;
    __syncthreads();
    sm = 0.f;
    #pragma unroll
    for (int i = 0; i < 8; i++) sm += reds[i];

    float r = 1.f / sm;
    __half2 h0 = __floats2half2_rn(v.x * r, v.y * r);
    __half2 h1 = __floats2half2_rn(v.z * r, v.w * r);
    __half2* dst = reinterpret_cast<__half2*>(P + row * 1024 + tid * 4);
    dst[0] = h0; dst[1] = h1;
}

// ---------------------------------------------------------------------------
// Temporal attention: QKV packed [NPOS, 1536] fp16 (Q +0, K +512, V +1024).
// Block = one hw, 128 threads. O out [NPOS, 512] fp16.
// ---------------------------------------------------------------------------
__global__ void __launch_bounds__(128)
temporal_t(const __half* __restrict__ QKV, __half* __restrict__ Ot,
           const int* __restrict__ winp)
{
    __shared__ float kv[16][512];
    __shared__ float at[16][16];
    const int hw = blockIdx.x;
    const int tid = threadIdx.x;
    const int wid = tid >> 5, lane = tid & 31;
    const float scale = 0.04419417382415922f;

    for (int idx = tid; idx < 4096; idx += 128) {
        int t = idx >> 8, c2 = idx & 255;
        __half2 h = *reinterpret_cast<const __half2*>(QKV + ((long)(t*1024 + hw))*1536 + 512 + c2*2);
        float2 f = __half22float2(h);
        kv[t][c2*2] = f.x; kv[t][c2*2+1] = f.y;
    }
    __syncthreads();

    #pragma unroll
    for (int ii = 0; ii < 4; ii++) {
        int i = wid + ii*4;
        float qv[16];
        const __half* qr = QKV + ((long)(i*1024 + hw)) * 1536;
        #pragma unroll
        for (int u = 0; u < 16; u++) qv[u] = __half2float(qr[lane + 32*u]);
        #pragma unroll
        for (int j = 0; j < 16; j++) {
            float s = 0.f;
            #pragma unroll
            for (int u = 0; u < 16; u++) s += qv[u] * kv[j][lane + 32*u];
            #pragma unroll
            for (int o = 16; o; o >>= 1) s += __shfl_xor_sync(0xffffffffu, s, o);
            if (lane == 0) at[i][j] = s * scale;
        }
    }
    __syncthreads();

    int win = winp ? *winp : 8;
    if (tid < 16) {
        int i = tid;
        float mx = -3.0e38f;
        #pragma unroll
        for (int j = 0; j < 16; j++) {
            bool ok = (j <= i) && (win <= 0 || (i - j) < win);
            if (ok) mx = fmaxf(mx, at[i][j]);
        }
        float sum = 0.f, e[16];
        #pragma unroll
        for (int j = 0; j < 16; j++) {
            bool ok = (j <= i) && (win <= 0 || (i - j) < win);
            e[j] = ok ? __expf(at[i][j] - mx) : 0.f;
            sum += e[j];
        }
        float rinv = 1.f / sum;
        #pragma unroll
        for (int j = 0; j < 16; j++) at[i][j] = e[j] * rinv;
    }
    __syncthreads();

    for (int idx = tid; idx < 4096; idx += 128) {
        int t = idx >> 8, c2 = idx & 255;
        __half2 h = *reinterpret_cast<const __half2*>(QKV + ((long)(t*1024 + hw))*1536 + 1024 + c2*2);
        float2 f = __half22float2(h);
        kv[t][c2*2] = f.x; kv[t][c2*2+1] = f.y;
    }
    __syncthreads();

    #pragma unroll
    for (int ii = 0; ii < 4; ii++) {
        int i = wid + ii*4;
        float a[16];
        #pragma unroll
        for (int j = 0; j < 16; j++) a[j] = at[i][j];
        __half* orow = Ot + ((long)(i*1024 + hw)) * 512;
        #pragma unroll
        for (int u = 0; u < 16; u++) {
            float o = 0.f;
            #pragma unroll
            for (int j = 0; j < 16; j++) o += a[j] * kv[j][lane + 32*u];
            orow[lane + 32*u] = __float2half_rn(o);
        }
    }
}

// ---------------------------------------------------------------------------
// Transpose: out[c][r] = in[r][c], in is [R, C_] (fp32)
// ---------------------------------------------------------------------------
__global__ void transpose_k(const float* __restrict__ in, float* __restrict__ out,
                            int R, int C_)
{
    __shared__ float t[32][33];
    int bx = blockIdx.x * 32;
    int by = blockIdx.y * 32;
    int tx = threadIdx.x, ty = threadIdx.y;
    #pragma unroll
    for (int i = 0; i < 4; i++)
        t[ty + 8*i][tx] = in[(long)(by + ty + 8*i) * C_ + bx + tx];
    __syncthreads();
    #pragma unroll
    for (int i = 0; i < 4; i++)
        out[(long)(bx + ty + 8*i) * R + by + tx] = t[tx][ty + 8*i];
}

// ---------------------------------------------------------------------------
extern "C" void kernel_launch(void* const* d_in, const int* in_sizes, int n_in,
                              void* d_out, int out_size)
{
    const float* x     = (const float*)d_in[0];
    const float* qs_w  = (const float*)d_in[1];
    const float* qs_b  = (const float*)d_in[2];
    const float* ks_w  = (const float*)d_in[3];
    const float* ks_b  = (const float*)d_in[4];
    const float* vs_w  = (const float*)d_in[5];
    const float* vs_b  = (const float*)d_in[6];
    const float* ps_w  = (const float*)d_in[7];
    const float* ps_b  = (const float*)d_in[8];
    const float* qt_w  = (const float*)d_in[9];
    const float* qt_b  = (const float*)d_in[10];
    const float* kt_w  = (const float*)d_in[11];
    const float* kt_b  = (const float*)d_in[12];
    const float* vt_w  = (const float*)d_in[13];
    const float* vt_b  = (const float*)d_in[14];
    const float* pt_w  = (const float*)d_in[15];
    const float* pt_b  = (const float*)d_in[16];
    const float* gm_s  = (const float*)d_in[17];
    const float* gm_t  = (const float*)d_in[18];
    const int*   winp  = (n_in > 19) ? (const int*)d_in[19] : nullptr;
    float* out = (float*)d_out;

    float *XT, *X1, *S, *BC;
    __half *H, *QKV, *V, *O, *P, *W;
    cudaGetSymbolAddress((void**)&XT,  g_XT);
    cudaGetSymbolAddress((void**)&X1,  g_X1);
    cudaGetSymbolAddress((void**)&S,   g_S);
    cudaGetSymbolAddress((void**)&BC,  g_BC);
    cudaGetSymbolAddress((void**)&H,   g_H);
    cudaGetSymbolAddress((void**)&QKV, g_QKV);
    cudaGetSymbolAddress((void**)&V,   g_V);
    cudaGetSymbolAddress((void**)&O,   g_O);
    cudaGetSymbolAddress((void**)&P,   g_P);
    cudaGetSymbolAddress((void**)&W,   g_W);

    static int attr_set = 0;
    if (!attr_set) {
        cudaFuncSetAttribute(gemm_h<true>,  cudaFuncAttributeMaxDynamicSharedMemorySize, GDSMEM);
        cudaFuncSetAttribute(gemm_h<false>, cudaFuncAttributeMaxDynamicSharedMemorySize, GDSMEM);
        cudaFuncSetAttribute(trms, cudaFuncAttributeMaxDynamicSharedMemorySize, TRMS_SMEM);
        attr_set = 1;
    }

    const float scale = 0.04419417382415922f;   // 512^-0.5
    const long ZB  = 1024L * 512;               // O per-t row-block stride (ld 512)
    const long ZQK = 1024L * 1024;              // QK per-t stride (ld 1024)
    const long ZS  = 1L << 20;                  // S/P per-t stride
    const long WS  = 512L * 512;

    // weights -> fp16 + bias packing
    convw<<<8192, 256>>>(qs_w, ks_w, vs_w, ps_w, qt_w, kt_w, vt_w, pt_w,
                         qs_b, ks_b, qt_b, kt_b, vt_b, W, BC);
    // x -> XT [n,c] + H = rms(x) fp16
    trms<<<512, 256, TRMS_SMEM>>>(x, XT, H, gm_s);

    // ---- spatial ----
    // QK fused: B rows = [qs; ks] (contiguous in W), out [n, 1024]
    gemm_h<true><<<dim3(8, 128, 1), 256, GDSMEM>>>(H, 512, 0,  W, 512, 0,
        QKV, 1024, 0, BC, 0, nullptr, 512, 1.f);
    // V in [c, n] layout
    gemm_h<true><<<dim3(128, 4, 1), 256, GDSMEM>>>(W + 2*WS, 512, 0,  H, 512, 0,
        V, NPOS, 0, vs_b, 1, nullptr, 512, 1.f);
    // scores S[t][l][m] fp32: A = Q (cols 0-511), B = K (cols 512-1023)
    gemm_h<false><<<dim3(8, 8, 16), 256, GDSMEM>>>(QKV, 1024, ZQK,  QKV + 512, 1024, ZQK,
        S, 1024, ZS, nullptr, 0, nullptr, 512, scale);
    softmax1024<<<16*1024, 256>>>(S, P);
    // O[t*1024+l][c] = sum_m P[l][m] V[c][t*1024+m]
    gemm_h<true><<<dim3(4, 8, 16), 256, GDSMEM>>>(P, 1024, ZS,  V, NPOS, 1024,
        O, 512, ZB, nullptr, 0, nullptr, 1024, 1.f);
    // X1 = XT + ps(O)  (fp32)
    gemm_h<false><<<dim3(4, 128, 1), 256, GDSMEM>>>(O, 512, 0,  W + 3*WS, 512, 0,
        X1, 512, 0, ps_b, 0, XT, 512, 1.f);

    // ---- temporal ----
    rms_rows<<<NPOS, 128>>>(X1, H, gm_t);
    // QKV fused: B rows = [qt; kt; vt], out [n, 1536]
    gemm_h<true><<<dim3(12, 128, 1), 256, GDSMEM>>>(H, 512, 0,  W + 4*WS, 512, 0,
        QKV, 1536, 0, BC + 2048, 0, nullptr, 512, 1.f);
    temporal_t<<<1024, 128>>>(QKV, O, winp);
    // Z = X1 + pt(O)  -> XT (fp32)
    gemm_h<false><<<dim3(4, 128, 1), 256, GDSMEM>>>(O, 512, 0,  W + 7*WS, 512, 0,
        XT, 512, 0, pt_b, 0, X1, 512, 1.f);
    // back to [c, n]
    transpose_k<<<dim3(16, 512), dim3(32, 8)>>>(XT, out, NPOS, 512);
}

// round 6
// speedup vs baseline: 5.7851x; 1.1106x over previous
#include <cuda_runtime.h>
#include <cuda_fp16.h>
#include <cstdint>
#include <math.h>

#define CDIM 512
#define NPOS 16384   // T*H*W
#define NELEM (CDIM*NPOS)

// ------------------------- scratch (device globals) -------------------------
__device__ float  g_X1[NELEM];            // fp32 residual carrier [c,n] after spatial
__device__ float  g_S [16*1024*1024];     // fp32 scores
__device__ __half g_H  [NELEM];           // rms output [n,c]
__device__ __half g_QKV[NPOS*1536];       // spatial QK (ld 1024) / temporal QKV (ld 1536)
__device__ __half g_V [NELEM];            // spatial V [c,n]
__device__ __half g_O [NELEM];            // attention out [n,c]
__device__ __half g_P [16*1024*1024];     // fp16 attention probs
__device__ __half g_W [8*CDIM*CDIM];      // fp16 weights (qs ks vs ps qt kt vt pt)
__device__ float  g_BC[4096];             // packed biases

// ------------------------- helpers -------------------------
__device__ __forceinline__ uint32_t smem_u32(const void* p){
    uint32_t a;
    asm("{ .reg .u64 t; cvta.to.shared.u64 t, %1; cvt.u32.u64 %0, t; }" : "=r"(a) : "l"(p));
    return a;
}
#define CP_ASYNC16(dst_u32, src_ptr) \
    asm volatile("cp.async.cg.shared.global [%0], [%1], 16;" :: "r"(dst_u32), "l"(src_ptr))
#define CP_COMMIT() asm volatile("cp.async.commit_group;" ::: "memory")
#define CP_WAIT0()  asm volatile("cp.async.wait_group 0;" ::: "memory")
#define CP_WAIT1()  asm volatile("cp.async.wait_group 1;" ::: "memory")

__device__ __forceinline__ void mma_f16(float* d, const uint32_t* a, const uint32_t* b){
    asm volatile(
        "mma.sync.aligned.m16n8k16.row.col.f32.f16.f16.f32 "
        "{%0,%1,%2,%3}, {%4,%5,%6,%7}, {%8,%9}, {%0,%1,%2,%3};"
        : "+f"(d[0]), "+f"(d[1]), "+f"(d[2]), "+f"(d[3])
        : "r"(a[0]), "r"(a[1]), "r"(a[2]), "r"(a[3]), "r"(b[0]), "r"(b[1]));
}
__device__ __forceinline__ void ldm_x4(uint32_t* r, uint32_t addr){
    asm volatile("ldmatrix.sync.aligned.m8n8.x4.shared.b16 {%0,%1,%2,%3}, [%4];"
        : "=r"(r[0]), "=r"(r[1]), "=r"(r[2]), "=r"(r[3]) : "r"(addr));
}

// ---------------------------------------------------------------------------
// fp16 mma.sync GEMM, both operands K-major:
//   C[z*czs + (y*128+r)*ldc + x*128 + s] =
//     scale * sum_k A[z*azs + (y*128+r)*lda + k] * B[z*bzs + (x*128+s)*ldb + k]
//     (+ bias[row or col], fp32) (+ Res fp32, only fp32 out)
// Block 128x128, BK=64, 256 threads (2x4 warps), 3-stage cp.async pipeline,
// one __syncthreads per chunk.
// ---------------------------------------------------------------------------
#define BK     64
#define ROWB   144                   // bytes per smem row (64 halfs = 128B + 16 pad)
#define STAGEB (128*ROWB*2)          // A+B per stage = 36864 B
#define GDSMEM (STAGEB*3)            // 110592 B

template<bool OUTH>
__global__ void __launch_bounds__(256, 2)
gemm_h(const __half* __restrict__ A, long lda, long azs,
       const __half* __restrict__ B, long ldb, long bzs,
       void* __restrict__ Cp, long ldc, long czs,
       const float* __restrict__ bias, int biasRow,
       const float* __restrict__ Res,
       int Kdim, float scale)
{
    extern __shared__ char sm[];
    const int tid  = threadIdx.x;
    const int wid  = tid >> 5;
    const int lane = tid & 31;
    const int wm   = wid >> 2;   // 0..1
    const int wn   = wid & 3;    // 0..3

    const long mRow0 = (long)blockIdx.y * 128;
    const long nCol0 = (long)blockIdx.x * 128;
    const __half* Ag = A + (long)blockIdx.z * azs + mRow0 * lda;
    const __half* Bg = B + (long)blockIdx.z * bzs + nCol0 * ldb;

    const uint32_t sbase = smem_u32(sm);
    const int lrow = tid >> 3;        // 0..31 (base for 128-row tiles, 4 iters)
    const int lq   = tid & 7;         // 16B octant within 128B row

    const uint32_t lmOff = (uint32_t)(lane & 15) * ROWB + (uint32_t)(lane >> 4) * 16;

    float acc[4][4][4];
    #pragma unroll
    for (int i = 0; i < 4; i++)
        #pragma unroll
        for (int j = 0; j < 4; j++)
            #pragma unroll
            for (int q = 0; q < 4; q++) acc[i][j][q] = 0.f;

    const int NC = Kdim >> 6;   // BK = 64

    #define LOADC(cc, st) do {                                                    \
        const long k0 = (long)(cc) * BK;                                          \
        uint32_t dA = sbase + (st)*STAGEB;                                        \
        uint32_t dB = dA + 128*ROWB;                                              \
        _Pragma("unroll")                                                         \
        for (int i = 0; i < 4; i++) {                                             \
            int row = lrow + i*32;                                                \
            CP_ASYNC16(dA + row*ROWB + lq*16, Ag + (long)row*lda + k0 + lq*8);    \
            CP_ASYNC16(dB + row*ROWB + lq*16, Bg + (long)row*ldb + k0 + lq*8);    \
        }                                                                         \
        CP_COMMIT();                                                              \
    } while(0)

    LOADC(0, 0); LOADC(1, 1);

    int st = 0;   // stage of chunk c (cycles 0,1,2)
    for (int c = 0; c < NC; ++c) {
        if (c + 1 < NC) CP_WAIT1(); else CP_WAIT0();
        __syncthreads();
        // safe: buffer (st+2)%3 held chunk c-1, whose compute finished before
        // the barrier above.
        if (c + 2 < NC) {
            int st2 = st + 2; if (st2 >= 3) st2 -= 3;
            LOADC(c + 2, st2);
        }

        const uint32_t stB = sbase + st*STAGEB;
        const uint32_t aAddr = stB + (uint32_t)(wm*64)*ROWB + lmOff;
        const uint32_t bAddr = stB + 128*ROWB + (uint32_t)(wn*32)*ROWB + lmOff;

        #pragma unroll
        for (int ks = 0; ks < 4; ks++) {
            const uint32_t kOff = ks*32;
            uint32_t af[4][4];
            #pragma unroll
            for (int mi = 0; mi < 4; mi++)
                ldm_x4(af[mi], aAddr + mi*(16*ROWB) + kOff);
            uint32_t bf[4][2];
            #pragma unroll
            for (int g = 0; g < 2; g++) {
                uint32_t bq[4];
                ldm_x4(bq, bAddr + g*(16*ROWB) + kOff);
                bf[2*g+0][0] = bq[0]; bf[2*g+1][0] = bq[1];
                bf[2*g+0][1] = bq[2]; bf[2*g+1][1] = bq[3];
            }
            #pragma unroll
            for (int mi = 0; mi < 4; mi++)
                #pragma unroll
                for (int ni = 0; ni < 4; ni++)
                    mma_f16(acc[mi][ni], af[mi], bf[ni]);
        }

        if (++st == 3) st = 0;
    }

    // ---- epilogue ----
    const long rBase = mRow0 + wm*64 + (lane >> 2);
    const long cBase = nCol0 + wn*32 + (lane & 3) * 2;
    #pragma unroll
    for (int mi = 0; mi < 4; mi++) {
        #pragma unroll
        for (int half_ = 0; half_ < 2; half_++) {
            const long r = rBase + mi*16 + half_*8;
            const float bvr = (bias && biasRow) ? __ldg(bias + r) : 0.f;
            const long rowOff = (long)blockIdx.z * czs + r * ldc;
            #pragma unroll
            for (int ni = 0; ni < 4; ni++) {
                const long cc = cBase + ni*8;
                float v0 = acc[mi][ni][half_*2 + 0] * scale;
                float v1 = acc[mi][ni][half_*2 + 1] * scale;
                if (bias) {
                    if (biasRow) { v0 += bvr; v1 += bvr; }
                    else { v0 += __ldg(bias + cc); v1 += __ldg(bias + cc + 1); }
                }
                if (OUTH) {
                    __half2 h = __floats2half2_rn(v0, v1);
                    *reinterpret_cast<__half2*>((__half*)Cp + rowOff + cc) = h;
                } else {
                    if (Res) {
                        float2 rv = *reinterpret_cast<const float2*>(Res + rowOff + cc);
                        v0 += rv.x; v1 += rv.y;
                    }
                    float2 o; o.x = v0; o.y = v1;
                    *reinterpret_cast<float2*>((float*)Cp + rowOff + cc) = o;
                }
            }
        }
    }
    #undef LOADC
}

// ---------------------------------------------------------------------------
// Weight fp32->fp16 conversion + bias packing
// ---------------------------------------------------------------------------
__global__ void convw(const float* __restrict__ w0, const float* __restrict__ w1,
                      const float* __restrict__ w2, const float* __restrict__ w3,
                      const float* __restrict__ w4, const float* __restrict__ w5,
                      const float* __restrict__ w6, const float* __restrict__ w7,
                      const float* __restrict__ qsb, const float* __restrict__ ksb,
                      const float* __restrict__ qtb, const float* __restrict__ ktb,
                      const float* __restrict__ vtb,
                      __half* __restrict__ W, float* __restrict__ BC)
{
    long i = (long)blockIdx.x * 256 + threadIdx.x;
    int sel = (int)(i >> 18);
    long off = i & 262143;
    const float* src;
    switch (sel) {
        case 0: src = w0; break; case 1: src = w1; break;
        case 2: src = w2; break; case 3: src = w3; break;
        case 4: src = w4; break; case 5: src = w5; break;
        case 6: src = w6; break; default: src = w7; break;
    }
    W[i] = __float2half_rn(src[off]);
    if (i < 2560) {
        long j = i;
        if      (j < 512)  BC[j]               = qsb[j];
        else if (j < 1024) BC[j]               = ksb[j - 512];
        else if (j < 1536) BC[2048 + (j-1024)] = qtb[j - 1024];
        else if (j < 2048) BC[2560 + (j-1536)] = ktb[j - 1536];
        else               BC[3072 + (j-2048)] = vtb[j - 2048];
    }
}

// ---------------------------------------------------------------------------
// Fused transpose + RMS: X [c,n] fp32 -> H [n,c] fp16 (rms over c per position)
// Block = 32 positions, 256 threads, 512x33 smem tile.
// ---------------------------------------------------------------------------
#define TRMS_SMEM (512*33*4)
__global__ void __launch_bounds__(256)
trms(const float* __restrict__ X, __half* __restrict__ H,
     const float* __restrict__ gamma)
{
    extern __shared__ float ts[];   // [512][33]
    __shared__ float red[8][32];
    __shared__ float invs[32];
    const int n0 = blockIdx.x * 32;
    const int tid = threadIdx.x;

    for (int idx = tid; idx < 4096; idx += 256) {
        int c = idx >> 3, q = idx & 7;
        float4 v = *reinterpret_cast<const float4*>(X + (long)c*NPOS + n0 + q*4);
        float* row = ts + c*33 + q*4;
        row[0]=v.x; row[1]=v.y; row[2]=v.z; row[3]=v.w;
    }
    __syncthreads();
    {
        int col = tid & 31, seg = tid >> 5;
        float ss = 0.f;
        #pragma unroll 8
        for (int c = seg*64; c < seg*64 + 64; c++) {
            float v = ts[c*33 + col]; ss += v*v;
        }
        red[seg][col] = ss;
    }
    __syncthreads();
    if (tid < 32) {
        float ss = 0.f;
        #pragma unroll
        for (int s = 0; s < 8; s++) ss += red[s][tid];
        invs[tid] = 22.62741699796952f / fmaxf(sqrtf(ss), 1e-12f);
    }
    __syncthreads();
    for (int idx = tid; idx < 16384; idx += 256) {
        int nl = idx >> 9, c = idx & 511;
        float v = ts[c*33 + nl];
        H[(long)(n0 + nl) * 512 + c] = __float2half_rn(v * invs[nl] * gamma[c]);
    }
}

// ---------------------------------------------------------------------------
// Softmax over 1024-long fp32 rows -> fp16 probs
// ---------------------------------------------------------------------------
__global__ void softmax1024(const float* __restrict__ S, __half* __restrict__ P)
{
    size_t row = blockIdx.x;
    const float4* p = reinterpret_cast<const float4*>(S + row * 1024);
    int tid = threadIdx.x;
    float4 v = p[tid];

    __shared__ float redm[8];
    __shared__ float reds[8];

    float mx = fmaxf(fmaxf(v.x, v.y), fmaxf(v.z, v.w));
    #pragma unroll
    for (int o = 16; o; o >>= 1) mx = fmaxf(mx, __shfl_xor_sync(0xffffffffu, mx, o));
    if ((tid & 31) == 0) redm[tid >> 5] = mx;
    __syncthreads();
    mx = redm[0];
    #pragma unroll
    for (int i = 1; i < 8; i++) mx = fmaxf(mx, redm[i]);

    v.x = __expf(v.x - mx); v.y = __expf(v.y - mx);
    v.z = __expf(v.z - mx); v.w = __expf(v.w - mx);

    float sm = v.x + v.y + v.z + v.w;
    #pragma unroll
    for (int o = 16; o; o >>= 1) sm += __shfl_xor_sync(0xffffffffu, sm, o);
    if ((tid & 31) == 0) reds[tid >> 5] = sm;
    __syncthreads();
    sm = 0.f;
    #pragma unroll
    for (int i = 0; i < 8; i++) sm += reds[i];

    float r = 1.f / sm;
    __half2 h0 = __floats2half2_rn(v.x * r, v.y * r);
    __half2 h1 = __floats2half2_rn(v.z * r, v.w * r);
    __half2* dst = reinterpret_cast<__half2*>(P + row * 1024 + tid * 4);
    dst[0] = h0; dst[1] = h1;
}

// ---------------------------------------------------------------------------
// Temporal attention: QKV packed [NPOS, 1536] fp16 (Q +0, K +512, V +1024).
// Block = one hw, 128 threads. O out [NPOS, 512] fp16.
// ---------------------------------------------------------------------------
__global__ void __launch_bounds__(128)
temporal_t(const __half* __restrict__ QKV, __half* __restrict__ Ot,
           const int* __restrict__ winp)
{
    __shared__ float kv[16][512];
    __shared__ float at[16][16];
    const int hw = blockIdx.x;
    const int tid = threadIdx.x;
    const int wid = tid >> 5, lane = tid & 31;
    const float scale = 0.04419417382415922f;

    for (int idx = tid; idx < 4096; idx += 128) {
        int t = idx >> 8, c2 = idx & 255;
        __half2 h = *reinterpret_cast<const __half2*>(QKV + ((long)(t*1024 + hw))*1536 + 512 + c2*2);
        float2 f = __half22float2(h);
        kv[t][c2*2] = f.x; kv[t][c2*2+1] = f.y;
    }
    __syncthreads();

    #pragma unroll
    for (int ii = 0; ii < 4; ii++) {
        int i = wid + ii*4;
        float qv[16];
        const __half* qr = QKV + ((long)(i*1024 + hw)) * 1536;
        #pragma unroll
        for (int u = 0; u < 16; u++) qv[u] = __half2float(qr[lane + 32*u]);
        #pragma unroll
        for (int j = 0; j < 16; j++) {
            float s = 0.f;
            #pragma unroll
            for (int u = 0; u < 16; u++) s += qv[u] * kv[j][lane + 32*u];
            #pragma unroll
            for (int o = 16; o; o >>= 1) s += __shfl_xor_sync(0xffffffffu, s, o);
            if (lane == 0) at[i][j] = s * scale;
        }
    }
    __syncthreads();

    int win = winp ? *winp : 8;
    if (tid < 16) {
        int i = tid;
        float mx = -3.0e38f;
        #pragma unroll
        for (int j = 0; j < 16; j++) {
            bool ok = (j <= i) && (win <= 0 || (i - j) < win);
            if (ok) mx = fmaxf(mx, at[i][j]);
        }
        float sum = 0.f, e[16];
        #pragma unroll
        for (int j = 0; j < 16; j++) {
            bool ok = (j <= i) && (win <= 0 || (i - j) < win);
            e[j] = ok ? __expf(at[i][j] - mx) : 0.f;
            sum += e[j];
        }
        float rinv = 1.f / sum;
        #pragma unroll
        for (int j = 0; j < 16; j++) at[i][j] = e[j] * rinv;
    }
    __syncthreads();

    for (int idx = tid; idx < 4096; idx += 128) {
        int t = idx >> 8, c2 = idx & 255;
        __half2 h = *reinterpret_cast<const __half2*>(QKV + ((long)(t*1024 + hw))*1536 + 1024 + c2*2);
        float2 f = __half22float2(h);
        kv[t][c2*2] = f.x; kv[t][c2*2+1] = f.y;
    }
    __syncthreads();

    #pragma unroll
    for (int ii = 0; ii < 4; ii++) {
        int i = wid + ii*4;
        float a[16];
        #pragma unroll
        for (int j = 0; j < 16; j++) a[j] = at[i][j];
        __half* orow = Ot + ((long)(i*1024 + hw)) * 512;
        #pragma unroll
        for (int u = 0; u < 16; u++) {
            float o = 0.f;
            #pragma unroll
            for (int j = 0; j < 16; j++) o += a[j] * kv[j][lane + 32*u];
            orow[lane + 32*u] = __float2half_rn(o);
        }
    }
}

// ---------------------------------------------------------------------------
extern "C" void kernel_launch(void* const* d_in, const int* in_sizes, int n_in,
                              void* d_out, int out_size)
{
    const float* x     = (const float*)d_in[0];
    const float* qs_w  = (const float*)d_in[1];
    const float* qs_b  = (const float*)d_in[2];
    const float* ks_w  = (const float*)d_in[3];
    const float* ks_b  = (const float*)d_in[4];
    const float* vs_w  = (const float*)d_in[5];
    const float* vs_b  = (const float*)d_in[6];
    const float* ps_w  = (const float*)d_in[7];
    const float* ps_b  = (const float*)d_in[8];
    const float* qt_w  = (const float*)d_in[9];
    const float* qt_b  = (const float*)d_in[10];
    const float* kt_w  = (const float*)d_in[11];
    const float* kt_b  = (const float*)d_in[12];
    const float* vt_w  = (const float*)d_in[13];
    const float* vt_b  = (const float*)d_in[14];
    const float* pt_w  = (const float*)d_in[15];
    const float* pt_b  = (const float*)d_in[16];
    const float* gm_s  = (const float*)d_in[17];
    const float* gm_t  = (const float*)d_in[18];
    const int*   winp  = (n_in > 19) ? (const int*)d_in[19] : nullptr;
    float* out = (float*)d_out;

    float *X1, *S, *BC;
    __half *H, *QKV, *V, *O, *P, *W;
    cudaGetSymbolAddress((void**)&X1,  g_X1);
    cudaGetSymbolAddress((void**)&S,   g_S);
    cudaGetSymbolAddress((void**)&BC,  g_BC);
    cudaGetSymbolAddress((void**)&H,   g_H);
    cudaGetSymbolAddress((void**)&QKV, g_QKV);
    cudaGetSymbolAddress((void**)&V,   g_V);
    cudaGetSymbolAddress((void**)&O,   g_O);
    cudaGetSymbolAddress((void**)&P,   g_P);
    cudaGetSymbolAddress((void**)&W,   g_W);

    static int attr_set = 0;
    if (!attr_set) {
        cudaFuncSetAttribute(gemm_h<true>,  cudaFuncAttributeMaxDynamicSharedMemorySize, GDSMEM);
        cudaFuncSetAttribute(gemm_h<false>, cudaFuncAttributeMaxDynamicSharedMemorySize, GDSMEM);
        cudaFuncSetAttribute(trms, cudaFuncAttributeMaxDynamicSharedMemorySize, TRMS_SMEM);
        attr_set = 1;
    }

    const float scale = 0.04419417382415922f;   // 512^-0.5
    const long ZB  = 1024L * 512;               // O per-t row-block stride (ld 512)
    const long ZQK = 1024L * 1024;              // QK per-t stride (ld 1024)
    const long ZS  = 1L << 20;                  // S/P per-t stride
    const long WS  = 512L * 512;

    // weights -> fp16 + bias packing
    convw<<<8192, 256>>>(qs_w, ks_w, vs_w, ps_w, qt_w, kt_w, vt_w, pt_w,
                         qs_b, ks_b, qt_b, kt_b, vt_b, W, BC);
    // H = rms(x) in [n,c] fp16 (residual stays as x in [c,n])
    trms<<<512, 256, TRMS_SMEM>>>(x, H, gm_s);

    // ---- spatial ----
    // QK fused: B rows = [qs; ks], out [n, 1024]
    gemm_h<true><<<dim3(8, 128, 1), 256, GDSMEM>>>(H, 512, 0,  W, 512, 0,
        QKV, 1024, 0, BC, 0, nullptr, 512, 1.f);
    // V in [c, n] layout
    gemm_h<true><<<dim3(128, 4, 1), 256, GDSMEM>>>(W + 2*WS, 512, 0,  H, 512, 0,
        V, NPOS, 0, vs_b, 1, nullptr, 512, 1.f);
    // scores S[t][l][m] fp32: A = Q (cols 0-511), B = K (cols 512-1023)
    gemm_h<false><<<dim3(8, 8, 16), 256, GDSMEM>>>(QKV, 1024, ZQK,  QKV + 512, 1024, ZQK,
        S, 1024, ZS, nullptr, 0, nullptr, 512, scale);
    softmax1024<<<16*1024, 256>>>(S, P);
    // O[t*1024+l][c] = sum_m P[l][m] V[c][t*1024+m]  (out [n,c] fp16)
    gemm_h<true><<<dim3(4, 8, 16), 256, GDSMEM>>>(P, 1024, ZS,  V, NPOS, 1024,
        O, 512, ZB, nullptr, 0, nullptr, 1024, 1.f);
    // X1c[c][n] = x[c][n] + ps(O): A = ps_w (M=512 c rows), B = O (N=16384 n rows)
    gemm_h<false><<<dim3(128, 4, 1), 256, GDSMEM>>>(W + 3*WS, 512, 0,  O, 512, 0,
        X1, NPOS, 0, ps_b, 1, x, 512, 1.f);

    // ---- temporal ----
    trms<<<512, 256, TRMS_SMEM>>>(X1, H, gm_t);
    // QKV fused: B rows = [qt; kt; vt], out [n, 1536]
    gemm_h<true><<<dim3(12, 128, 1), 256, GDSMEM>>>(H, 512, 0,  W + 4*WS, 512, 0,
        QKV, 1536, 0, BC + 2048, 0, nullptr, 512, 1.f);
    temporal_t<<<1024, 128>>>(QKV, O, winp);
    // out[c][n] = X1c[c][n] + pt(O): direct to d_out, no final transpose
    gemm_h<false><<<dim3(128, 4, 1), 256, GDSMEM>>>(W + 7*WS, 512, 0,  O, 512, 0,
        out, NPOS, 0, pt_b, 1, X1, 512, 1.f);
}